// round 3
// baseline (speedup 1.0000x reference)
#include <cuda_runtime.h>
#include <cuda_bf16.h>
#include <math.h>

#define MAX_N 100000
#define MAX_E 3200000
#define MAX_G 256
#define HDIM 64

// ---------------- device scratch (no runtime allocation allowed) ----------------
__device__ __align__(16) float d_deg[MAX_N];
__device__ __align__(16) float d_dinv[MAX_N];
__device__ __align__(16) float d_enorm[MAX_E];
__device__ __align__(16) float d_buf0[MAX_N * HDIM];   // hw scratch
__device__ __align__(16) float d_buf1[MAX_N * HDIM];   // layer io
__device__ __align__(16) float d_buf2[MAX_N * HDIM];   // layer io
__device__ __align__(16) float d_psum[MAX_G * HDIM];
__device__ __align__(16) float d_pcnt[MAX_G];

// ---------------- helpers ----------------
__device__ __forceinline__ void red_add_v4(float4* addr, float4 v) {
    asm volatile("red.global.add.v4.f32 [%0], {%1,%2,%3,%4};"
                 :: "l"(addr), "f"(v.x), "f"(v.y), "f"(v.z), "f"(v.w)
                 : "memory");
}

// ---------------- kernels ----------------
__global__ void zero_kernel(float* deg, float* psum, float* pcnt, int n, int g) {
    int i = blockIdx.x * blockDim.x + threadIdx.x;
    if (i < n) deg[i] = 0.f;
    if (i < g * HDIM) psum[i] = 0.f;
    if (i < g) pcnt[i] = 0.f;
}

// count in-degree of dst (edge_index is int32: row 0 = src, row 1 = dst)
__global__ void deg_kernel(const int* __restrict__ dst,
                           float* __restrict__ deg, int nE) {
    int e = blockIdx.x * blockDim.x + threadIdx.x;
    if (e >= nE) return;
    atomicAdd(&deg[dst[e]], 1.f);
}

__global__ void dinv_kernel(const float* __restrict__ deg, float* __restrict__ dinv, int n) {
    int i = blockIdx.x * blockDim.x + threadIdx.x;
    if (i >= n) return;
    dinv[i] = rsqrtf(deg[i] + 1.0f);
}

__global__ void enorm_kernel(const int* __restrict__ src, const int* __restrict__ dst,
                             const float* __restrict__ dinv, float* __restrict__ w, int nE) {
    int e = blockIdx.x * blockDim.x + threadIdx.x;
    if (e >= nE) return;
    w[e] = dinv[src[e]] * dinv[dst[e]];
}

// layer-1 GEMM: x [N,5] @ W1 [5,64]; also initialize agg with self-loop term
__global__ void gemm5(const float* __restrict__ x, const float* __restrict__ W,
                      const float* __restrict__ dinv,
                      float* __restrict__ hw, float* __restrict__ agg, int n) {
    int i = blockIdx.x * blockDim.x + threadIdx.x;
    if (i >= n * HDIM) return;
    int node = i >> 6;
    int c = i & 63;
    float acc = 0.f;
#pragma unroll
    for (int k = 0; k < 5; k++)
        acc += x[node * 5 + k] * W[k * HDIM + c];
    hw[i] = acc;
    float di = dinv[node];
    agg[i] = acc * di * di;
}

// 64x64 GEMM: block = 64 nodes x 64 channels, 256 threads, 4x4 micro-tiles.
// Also writes agg = hw * snorm (self-loop init).
__global__ void gemm64(const float* __restrict__ in, const float* __restrict__ W,
                       const float* __restrict__ dinv,
                       float* __restrict__ hw, float* __restrict__ agg, int n) {
    __shared__ float sA[64][65];
    __shared__ __align__(16) float sB[64][64];
    int block_row = blockIdx.x * 64;
    int tid = threadIdx.x;

    for (int i = tid; i < 4096; i += 256)
        sB[i >> 6][i & 63] = W[i];
    for (int i = tid; i < 4096; i += 256) {
        int r = i >> 6, c = i & 63;
        int node = block_row + r;
        sA[r][c] = (node < n) ? in[node * HDIM + c] : 0.f;
    }
    __syncthreads();

    int tr = (tid >> 4) * 4;
    int tc = (tid & 15) * 4;
    float acc[4][4];
#pragma unroll
    for (int i = 0; i < 4; i++)
#pragma unroll
        for (int j = 0; j < 4; j++) acc[i][j] = 0.f;

#pragma unroll 8
    for (int k = 0; k < 64; k++) {
        float a0 = sA[tr + 0][k];
        float a1 = sA[tr + 1][k];
        float a2 = sA[tr + 2][k];
        float a3 = sA[tr + 3][k];
        float4 b = *reinterpret_cast<const float4*>(&sB[k][tc]);
        acc[0][0] += a0 * b.x; acc[0][1] += a0 * b.y; acc[0][2] += a0 * b.z; acc[0][3] += a0 * b.w;
        acc[1][0] += a1 * b.x; acc[1][1] += a1 * b.y; acc[1][2] += a1 * b.z; acc[1][3] += a1 * b.w;
        acc[2][0] += a2 * b.x; acc[2][1] += a2 * b.y; acc[2][2] += a2 * b.z; acc[2][3] += a2 * b.w;
        acc[3][0] += a3 * b.x; acc[3][1] += a3 * b.y; acc[3][2] += a3 * b.z; acc[3][3] += a3 * b.w;
    }

#pragma unroll
    for (int i = 0; i < 4; i++) {
        int node = block_row + tr + i;
        if (node >= n) break;
        float di = dinv[node];
        float sn = di * di;
        float4 v = make_float4(acc[i][0], acc[i][1], acc[i][2], acc[i][3]);
        *reinterpret_cast<float4*>(&hw[node * HDIM + tc]) = v;
        float4 a = make_float4(v.x * sn, v.y * sn, v.z * sn, v.w * sn);
        *reinterpret_cast<float4*>(&agg[node * HDIM + tc]) = a;
    }
}

// edge scatter: 16 threads per edge, float4 gather + vector reduction
__global__ void edge_agg(const int* __restrict__ src, const int* __restrict__ dst,
                         const float* __restrict__ w,
                         const float4* __restrict__ hw4, float4* __restrict__ agg4,
                         int nE) {
    long long t = (long long)blockIdx.x * blockDim.x + threadIdx.x;
    long long e = t >> 4;
    int j = (int)(t & 15);
    if (e >= nE) return;
    int s = src[e];
    int d = dst[e];
    float ww = w[e];
    float4 v = hw4[(long long)s * 16 + j];
    float4 r = make_float4(v.x * ww, v.y * ww, v.z * ww, v.w * ww);
    red_add_v4(&agg4[(long long)d * 16 + j], r);
}

// BN(eval) + ReLU, in place; GCN bias b folded into the affine
__global__ void bn_relu(float4* __restrict__ agg,
                        const float* __restrict__ b, const float* __restrict__ g,
                        const float* __restrict__ be, const float* __restrict__ rm,
                        const float* __restrict__ rv, int n) {
    int i = blockIdx.x * blockDim.x + threadIdx.x;
    if (i >= n * 16) return;
    int cb = (i & 15) * 4;
    float4 v = agg[i];
    float out[4];
    float in[4] = {v.x, v.y, v.z, v.w};
#pragma unroll
    for (int k = 0; k < 4; k++) {
        int c = cb + k;
        float alpha = g[c] * rsqrtf(rv[c] + 1e-5f);
        float beta = (b[c] - rm[c]) * alpha + be[c];
        out[k] = fmaxf(in[k] * alpha + beta, 0.f);
    }
    agg[i] = make_float4(out[0], out[1], out[2], out[3]);
}

// mean pooling via atomics (batch is int32)
__global__ void pool_kernel(const float4* __restrict__ h4, const int* __restrict__ batch,
                            float4* __restrict__ psum4, float* __restrict__ pcnt, int n) {
    long long t = (long long)blockIdx.x * blockDim.x + threadIdx.x;
    int node = (int)(t >> 4);
    int j = (int)(t & 15);
    if (node >= n) return;
    int g = batch[node];
    float4 v = h4[(long long)node * 16 + j];
    red_add_v4(&psum4[g * 16 + j], v);
    if (j == 0) atomicAdd(&pcnt[g], 1.f);
}

// final MLP: one block (32 threads) per graph
__global__ void mlp_kernel(const float* __restrict__ psum, const float* __restrict__ pcnt,
                           const float* __restrict__ Wf1, const float* __restrict__ bf1,
                           const float* __restrict__ Wf2, const float* __restrict__ bf2,
                           float* __restrict__ out) {
    int g = blockIdx.x;
    int t = threadIdx.x;  // 0..31
    __shared__ float p[64];
    __shared__ float hh[32];
    float cnt = fmaxf(pcnt[g], 1.f);
    float inv = 1.f / cnt;
    p[t] = psum[g * HDIM + t] * inv;
    p[t + 32] = psum[g * HDIM + t + 32] * inv;
    __syncwarp();
    float acc = bf1[t];
#pragma unroll
    for (int k = 0; k < 64; k++)
        acc += p[k] * Wf1[k * 32 + t];
    hh[t] = fmaxf(acc, 0.f);
    __syncwarp();
    if (t < 2) {
        float o = bf2[t];
#pragma unroll
        for (int k = 0; k < 32; k++)
            o += hh[k] * Wf2[k * 2 + t];
        out[g * 2 + t] = 1.f / (1.f + expf(-o));
    }
}

// ---------------- launch ----------------
extern "C" void kernel_launch(void* const* d_in, const int* in_sizes, int n_in,
                              void* d_out, int out_size) {
    const float* x     = (const float*)d_in[0];
    const int*   ei    = (const int*)d_in[1];    // int32! (JAX x64 disabled)
    const int*   batch = (const int*)d_in[2];    // int32!
    const float* W1 = (const float*)d_in[3];
    const float* b1 = (const float*)d_in[4];
    const float* g1 = (const float*)d_in[5];
    const float* be1 = (const float*)d_in[6];
    const float* rm1 = (const float*)d_in[7];
    const float* rv1 = (const float*)d_in[8];
    const float* W2 = (const float*)d_in[9];
    const float* b2 = (const float*)d_in[10];
    const float* g2 = (const float*)d_in[11];
    const float* be2 = (const float*)d_in[12];
    const float* rm2 = (const float*)d_in[13];
    const float* rv2 = (const float*)d_in[14];
    const float* W3 = (const float*)d_in[15];
    const float* b3 = (const float*)d_in[16];
    const float* g3 = (const float*)d_in[17];
    const float* be3 = (const float*)d_in[18];
    const float* rm3 = (const float*)d_in[19];
    const float* rv3 = (const float*)d_in[20];
    const float* Wf1 = (const float*)d_in[21];
    const float* bf1 = (const float*)d_in[22];
    const float* Wf2 = (const float*)d_in[23];
    const float* bf2 = (const float*)d_in[24];

    int n = in_sizes[0] / 5;
    int e = in_sizes[1] / 2;
    int g = out_size / 2;

    const int* srcp = ei;        // row 0
    const int* dstp = ei + e;    // row 1

    float *deg, *dinv, *enorm, *buf0, *buf1, *buf2, *psum, *pcnt;
    cudaGetSymbolAddress((void**)&deg, d_deg);
    cudaGetSymbolAddress((void**)&dinv, d_dinv);
    cudaGetSymbolAddress((void**)&enorm, d_enorm);
    cudaGetSymbolAddress((void**)&buf0, d_buf0);
    cudaGetSymbolAddress((void**)&buf1, d_buf1);
    cudaGetSymbolAddress((void**)&buf2, d_buf2);
    cudaGetSymbolAddress((void**)&psum, d_psum);
    cudaGetSymbolAddress((void**)&pcnt, d_pcnt);

    const int BS = 256;
    int zero_elems = n > g * HDIM ? n : g * HDIM;

    zero_kernel<<<(zero_elems + BS - 1) / BS, BS>>>(deg, psum, pcnt, n, g);
    deg_kernel<<<(e + BS - 1) / BS, BS>>>(dstp, deg, e);
    dinv_kernel<<<(n + BS - 1) / BS, BS>>>(deg, dinv, n);
    enorm_kernel<<<(e + BS - 1) / BS, BS>>>(srcp, dstp, dinv, enorm, e);

    long long et = (long long)e * 16;
    int eg = (int)((et + BS - 1) / BS);
    int ng16 = (n * 16 + BS - 1) / BS;

    // layer 1: in=x, hw=buf0, agg=buf1
    gemm5<<<(n * HDIM + BS - 1) / BS, BS>>>(x, W1, dinv, buf0, buf1, n);
    edge_agg<<<eg, BS>>>(srcp, dstp, enorm, (const float4*)buf0, (float4*)buf1, e);
    bn_relu<<<ng16, BS>>>((float4*)buf1, b1, g1, be1, rm1, rv1, n);

    // layer 2: in=buf1, hw=buf0, agg=buf2
    gemm64<<<(n + 63) / 64, BS>>>(buf1, W2, dinv, buf0, buf2, n);
    edge_agg<<<eg, BS>>>(srcp, dstp, enorm, (const float4*)buf0, (float4*)buf2, e);
    bn_relu<<<ng16, BS>>>((float4*)buf2, b2, g2, be2, rm2, rv2, n);

    // layer 3: in=buf2, hw=buf0, agg=buf1
    gemm64<<<(n + 63) / 64, BS>>>(buf2, W3, dinv, buf0, buf1, n);
    edge_agg<<<eg, BS>>>(srcp, dstp, enorm, (const float4*)buf0, (float4*)buf1, e);
    bn_relu<<<ng16, BS>>>((float4*)buf1, b3, g3, be3, rm3, rv3, n);

    // pool + MLP
    pool_kernel<<<ng16, BS>>>((const float4*)buf1, batch, (float4*)psum, pcnt, n);
    mlp_kernel<<<g, 32>>>(psum, pcnt, Wf1, bf1, Wf2, bf2, (float*)d_out);
}

// round 4
// speedup vs baseline: 1.6306x; 1.6306x over previous
#include <cuda_runtime.h>
#include <cuda_bf16.h>
#include <math.h>

#define MAX_N 100000
#define MAX_E 3200000
#define MAX_G 256
#define HDIM 64

// ---------------- device scratch ----------------
__device__ __align__(16) int   d_cnt[MAX_N];
__device__ __align__(16) int   d_rowptr[MAX_N + 1];
__device__ __align__(16) int   d_cursor[MAX_N];
__device__ __align__(16) int   d_col[MAX_E];
__device__ __align__(16) float d_wgt[MAX_E];
__device__ __align__(16) float d_dinv[MAX_N];
__device__ __align__(16) float d_buf0[MAX_N * HDIM];   // hw scratch
__device__ __align__(16) float d_buf1[MAX_N * HDIM];
__device__ __align__(16) float d_buf2[MAX_N * HDIM];
__device__ __align__(16) float d_psum[MAX_G * HDIM];
__device__ __align__(16) float d_pcnt[MAX_G];

__device__ __forceinline__ void red_add_v4(float4* addr, float4 v) {
    asm volatile("red.global.add.v4.f32 [%0], {%1,%2,%3,%4};"
                 :: "l"(addr), "f"(v.x), "f"(v.y), "f"(v.z), "f"(v.w)
                 : "memory");
}

// ---------------- prep kernels ----------------
__global__ void zero_kernel(int* cnt, float* psum, float* pcnt, int n, int g) {
    int i = blockIdx.x * blockDim.x + threadIdx.x;
    if (i < n) cnt[i] = 0;
    if (i < g * HDIM) psum[i] = 0.f;
    if (i < g) pcnt[i] = 0.f;
}

__global__ void count_kernel(const int* __restrict__ dst, int* __restrict__ cnt, int nE) {
    int e = blockIdx.x * blockDim.x + threadIdx.x;
    if (e >= nE) return;
    atomicAdd(&cnt[dst[e]], 1);
}

__global__ void count_batch_kernel(const int* __restrict__ batch, float* __restrict__ pcnt, int n) {
    int i = blockIdx.x * blockDim.x + threadIdx.x;
    if (i >= n) return;
    atomicAdd(&pcnt[batch[i]], 1.f);
}

__global__ void dinv_kernel(const int* __restrict__ cnt, float* __restrict__ dinv, int n) {
    int i = blockIdx.x * blockDim.x + threadIdx.x;
    if (i >= n) return;
    dinv[i] = rsqrtf((float)cnt[i] + 1.0f);
}

// single-block exclusive scan (1024 threads, warp-shuffle based)
__global__ void scan_kernel(const int* __restrict__ cnt, int* __restrict__ rowptr,
                            int* __restrict__ cursor, int n, int nE) {
    __shared__ int warp_sums[32];
    __shared__ int s_carry;
    int tid = threadIdx.x;
    int lane = tid & 31;
    int wid = tid >> 5;
    if (tid == 0) s_carry = 0;
    __syncthreads();

    for (int base = 0; base < n; base += 1024) {
        int i = base + tid;
        int v = (i < n) ? cnt[i] : 0;
        // warp inclusive scan
        int incl = v;
#pragma unroll
        for (int off = 1; off < 32; off <<= 1) {
            int t = __shfl_up_sync(0xffffffffu, incl, off);
            if (lane >= off) incl += t;
        }
        if (lane == 31) warp_sums[wid] = incl;
        __syncthreads();
        if (wid == 0) {
            int ws = warp_sums[lane];
            int wincl = ws;
#pragma unroll
            for (int off = 1; off < 32; off <<= 1) {
                int t = __shfl_up_sync(0xffffffffu, wincl, off);
                if (lane >= off) wincl += t;
            }
            warp_sums[lane] = wincl - ws;  // exclusive warp offset
        }
        __syncthreads();
        int excl = incl - v + warp_sums[wid] + s_carry;
        if (i < n) { rowptr[i] = excl; cursor[i] = excl; }
        __syncthreads();
        if (tid == 1023) s_carry = excl + v;
        __syncthreads();
    }
    if (tid == 0) rowptr[n] = nE;
}

// scatter edges into CSR (by dst); weight = dinv[src]*dinv[dst]
__global__ void scatter_kernel(const int* __restrict__ src, const int* __restrict__ dst,
                               const float* __restrict__ dinv,
                               int* __restrict__ cursor,
                               int* __restrict__ col, float* __restrict__ wgt, int nE) {
    int e = blockIdx.x * blockDim.x + threadIdx.x;
    if (e >= nE) return;
    int s = src[e];
    int d = dst[e];
    int idx = atomicAdd(&cursor[d], 1);
    col[idx] = s;
    wgt[idx] = dinv[s] * dinv[d];
}

// ---------------- GEMM kernels (write hw only) ----------------
__global__ void gemm5(const float* __restrict__ x, const float* __restrict__ W,
                      float* __restrict__ hw, int n) {
    int i = blockIdx.x * blockDim.x + threadIdx.x;
    if (i >= n * HDIM) return;
    int node = i >> 6;
    int c = i & 63;
    float acc = 0.f;
#pragma unroll
    for (int k = 0; k < 5; k++)
        acc += x[node * 5 + k] * W[k * HDIM + c];
    hw[i] = acc;
}

__global__ void gemm64(const float* __restrict__ in, const float* __restrict__ W,
                       float* __restrict__ hw, int n) {
    __shared__ float sA[64][65];
    __shared__ __align__(16) float sB[64][64];
    int block_row = blockIdx.x * 64;
    int tid = threadIdx.x;

    for (int i = tid; i < 4096; i += 256)
        sB[i >> 6][i & 63] = W[i];
    for (int i = tid; i < 4096; i += 256) {
        int r = i >> 6, c = i & 63;
        int node = block_row + r;
        sA[r][c] = (node < n) ? in[node * HDIM + c] : 0.f;
    }
    __syncthreads();

    int tr = (tid >> 4) * 4;
    int tc = (tid & 15) * 4;
    float acc[4][4];
#pragma unroll
    for (int i = 0; i < 4; i++)
#pragma unroll
        for (int j = 0; j < 4; j++) acc[i][j] = 0.f;

#pragma unroll 8
    for (int k = 0; k < 64; k++) {
        float a0 = sA[tr + 0][k];
        float a1 = sA[tr + 1][k];
        float a2 = sA[tr + 2][k];
        float a3 = sA[tr + 3][k];
        float4 b = *reinterpret_cast<const float4*>(&sB[k][tc]);
        acc[0][0] += a0 * b.x; acc[0][1] += a0 * b.y; acc[0][2] += a0 * b.z; acc[0][3] += a0 * b.w;
        acc[1][0] += a1 * b.x; acc[1][1] += a1 * b.y; acc[1][2] += a1 * b.z; acc[1][3] += a1 * b.w;
        acc[2][0] += a2 * b.x; acc[2][1] += a2 * b.y; acc[2][2] += a2 * b.z; acc[2][3] += a2 * b.w;
        acc[3][0] += a3 * b.x; acc[3][1] += a3 * b.y; acc[3][2] += a3 * b.z; acc[3][3] += a3 * b.w;
    }

#pragma unroll
    for (int i = 0; i < 4; i++) {
        int node = block_row + tr + i;
        if (node >= n) break;
        float4 v = make_float4(acc[i][0], acc[i][1], acc[i][2], acc[i][3]);
        *reinterpret_cast<float4*>(&hw[node * HDIM + tc]) = v;
    }
}

// ---------------- fused CSR aggregation + bias + BN + ReLU (+pool) ----------------
// 16 threads per node; thread j owns float4 channel group j (channels 4j..4j+3).
template <bool POOL>
__global__ void agg_fused(const int* __restrict__ rowptr,
                          const int* __restrict__ col, const float* __restrict__ wgt,
                          const float* __restrict__ dinv,
                          const float4* __restrict__ hw4,
                          float4* __restrict__ out4,
                          const float* __restrict__ b, const float* __restrict__ g,
                          const float* __restrict__ be, const float* __restrict__ rm,
                          const float* __restrict__ rv,
                          const int* __restrict__ batch, float4* __restrict__ psum4,
                          int n) {
    int t = blockIdx.x * blockDim.x + threadIdx.x;
    int node = t >> 4;
    int j = t & 15;
    if (node >= n) return;

    int beg = rowptr[node];
    int end = rowptr[node + 1];

    float di = dinv[node];
    float sn = di * di;
    float4 self = hw4[(size_t)node * 16 + j];
    float4 acc = make_float4(self.x * sn, self.y * sn, self.z * sn, self.w * sn);

    int k = beg;
#pragma unroll 1
    for (; k + 4 <= end; k += 4) {
        int c0 = __ldg(&col[k + 0]);
        int c1 = __ldg(&col[k + 1]);
        int c2 = __ldg(&col[k + 2]);
        int c3 = __ldg(&col[k + 3]);
        float w0 = __ldg(&wgt[k + 0]);
        float w1 = __ldg(&wgt[k + 1]);
        float w2 = __ldg(&wgt[k + 2]);
        float w3 = __ldg(&wgt[k + 3]);
        float4 v0 = hw4[(size_t)c0 * 16 + j];
        float4 v1 = hw4[(size_t)c1 * 16 + j];
        float4 v2 = hw4[(size_t)c2 * 16 + j];
        float4 v3 = hw4[(size_t)c3 * 16 + j];
        acc.x += w0 * v0.x + w1 * v1.x + w2 * v2.x + w3 * v3.x;
        acc.y += w0 * v0.y + w1 * v1.y + w2 * v2.y + w3 * v3.y;
        acc.z += w0 * v0.z + w1 * v1.z + w2 * v2.z + w3 * v3.z;
        acc.w += w0 * v0.w + w1 * v1.w + w2 * v2.w + w3 * v3.w;
    }
    for (; k < end; k++) {
        int c = __ldg(&col[k]);
        float w = __ldg(&wgt[k]);
        float4 v = hw4[(size_t)c * 16 + j];
        acc.x += w * v.x; acc.y += w * v.y; acc.z += w * v.z; acc.w += w * v.w;
    }

    // epilogue: (acc + b - rm) * g*rsqrt(rv+eps) + be, then ReLU
    int cb = j * 4;
    float o[4];
    float in[4] = {acc.x, acc.y, acc.z, acc.w};
#pragma unroll
    for (int q = 0; q < 4; q++) {
        int c = cb + q;
        float alpha = g[c] * rsqrtf(rv[c] + 1e-5f);
        float beta = (b[c] - rm[c]) * alpha + be[c];
        o[q] = fmaxf(in[q] * alpha + beta, 0.f);
    }
    float4 h = make_float4(o[0], o[1], o[2], o[3]);

    if (POOL) {
        int gg = batch[node];
        red_add_v4(&psum4[gg * 16 + j], h);
    } else {
        out4[(size_t)node * 16 + j] = h;
    }
}

// ---------------- final MLP ----------------
__global__ void mlp_kernel(const float* __restrict__ psum, const float* __restrict__ pcnt,
                           const float* __restrict__ Wf1, const float* __restrict__ bf1,
                           const float* __restrict__ Wf2, const float* __restrict__ bf2,
                           float* __restrict__ out) {
    int g = blockIdx.x;
    int t = threadIdx.x;  // 0..31
    __shared__ float p[64];
    __shared__ float hh[32];
    float cnt = fmaxf(pcnt[g], 1.f);
    float inv = 1.f / cnt;
    p[t] = psum[g * HDIM + t] * inv;
    p[t + 32] = psum[g * HDIM + t + 32] * inv;
    __syncwarp();
    float acc = bf1[t];
#pragma unroll
    for (int k = 0; k < 64; k++)
        acc += p[k] * Wf1[k * 32 + t];
    hh[t] = fmaxf(acc, 0.f);
    __syncwarp();
    if (t < 2) {
        float o = bf2[t];
#pragma unroll
        for (int k = 0; k < 32; k++)
            o += hh[k] * Wf2[k * 2 + t];
        out[g * 2 + t] = 1.f / (1.f + expf(-o));
    }
}

// ---------------- launch ----------------
extern "C" void kernel_launch(void* const* d_in, const int* in_sizes, int n_in,
                              void* d_out, int out_size) {
    const float* x     = (const float*)d_in[0];
    const int*   ei    = (const int*)d_in[1];    // int32
    const int*   batch = (const int*)d_in[2];    // int32
    const float* W1 = (const float*)d_in[3];
    const float* b1 = (const float*)d_in[4];
    const float* g1 = (const float*)d_in[5];
    const float* be1 = (const float*)d_in[6];
    const float* rm1 = (const float*)d_in[7];
    const float* rv1 = (const float*)d_in[8];
    const float* W2 = (const float*)d_in[9];
    const float* b2 = (const float*)d_in[10];
    const float* g2 = (const float*)d_in[11];
    const float* be2 = (const float*)d_in[12];
    const float* rm2 = (const float*)d_in[13];
    const float* rv2 = (const float*)d_in[14];
    const float* W3 = (const float*)d_in[15];
    const float* b3 = (const float*)d_in[16];
    const float* g3 = (const float*)d_in[17];
    const float* be3 = (const float*)d_in[18];
    const float* rm3 = (const float*)d_in[19];
    const float* rv3 = (const float*)d_in[20];
    const float* Wf1 = (const float*)d_in[21];
    const float* bf1 = (const float*)d_in[22];
    const float* Wf2 = (const float*)d_in[23];
    const float* bf2 = (const float*)d_in[24];

    int n = in_sizes[0] / 5;
    int e = in_sizes[1] / 2;
    int g = out_size / 2;

    const int* srcp = ei;
    const int* dstp = ei + e;

    int *cnt, *rowptr, *cursor, *colp;
    float *wgtp, *dinv, *buf0, *buf1, *buf2, *psum, *pcnt;
    cudaGetSymbolAddress((void**)&cnt, d_cnt);
    cudaGetSymbolAddress((void**)&rowptr, d_rowptr);
    cudaGetSymbolAddress((void**)&cursor, d_cursor);
    cudaGetSymbolAddress((void**)&colp, d_col);
    cudaGetSymbolAddress((void**)&wgtp, d_wgt);
    cudaGetSymbolAddress((void**)&dinv, d_dinv);
    cudaGetSymbolAddress((void**)&buf0, d_buf0);
    cudaGetSymbolAddress((void**)&buf1, d_buf1);
    cudaGetSymbolAddress((void**)&buf2, d_buf2);
    cudaGetSymbolAddress((void**)&psum, d_psum);
    cudaGetSymbolAddress((void**)&pcnt, d_pcnt);

    const int BS = 256;
    int zero_elems = n > g * HDIM ? n : g * HDIM;

    zero_kernel<<<(zero_elems + BS - 1) / BS, BS>>>(cnt, psum, pcnt, n, g);
    count_kernel<<<(e + BS - 1) / BS, BS>>>(dstp, cnt, e);
    count_batch_kernel<<<(n + BS - 1) / BS, BS>>>(batch, pcnt, n);
    dinv_kernel<<<(n + BS - 1) / BS, BS>>>(cnt, dinv, n);
    scan_kernel<<<1, 1024>>>(cnt, rowptr, cursor, n, e);
    scatter_kernel<<<(e + BS - 1) / BS, BS>>>(srcp, dstp, dinv, cursor, colp, wgtp, e);

    int ng16 = (n * 16 + BS - 1) / BS;

    // layer 1
    gemm5<<<(n * HDIM + BS - 1) / BS, BS>>>(x, W1, buf0, n);
    agg_fused<false><<<ng16, BS>>>(rowptr, colp, wgtp, dinv, (const float4*)buf0,
                                   (float4*)buf1, b1, g1, be1, rm1, rv1,
                                   batch, (float4*)psum, n);
    // layer 2
    gemm64<<<(n + 63) / 64, BS>>>(buf1, W2, buf0, n);
    agg_fused<false><<<ng16, BS>>>(rowptr, colp, wgtp, dinv, (const float4*)buf0,
                                   (float4*)buf2, b2, g2, be2, rm2, rv2,
                                   batch, (float4*)psum, n);
    // layer 3 (fused pooling)
    gemm64<<<(n + 63) / 64, BS>>>(buf2, W3, buf0, n);
    agg_fused<true><<<ng16, BS>>>(rowptr, colp, wgtp, dinv, (const float4*)buf0,
                                  (float4*)buf1, b3, g3, be3, rm3, rv3,
                                  batch, (float4*)psum, n);

    mlp_kernel<<<g, 32>>>(psum, pcnt, Wf1, bf1, Wf2, bf2, (float*)d_out);
}

// round 5
// speedup vs baseline: 2.1897x; 1.3429x over previous
#include <cuda_runtime.h>
#include <cuda_fp16.h>
#include <math.h>

#define MAX_N 100000
#define MAX_E 3200000
#define MAX_G 256
#define HDIM 64
#define NB1024 ((MAX_N + 1023) / 1024)

// ---------------- device scratch ----------------
__device__ __align__(16) int    d_cnt[MAX_N];
__device__ __align__(16) int    d_rowptr[MAX_N + 1];
__device__ __align__(16) int    d_cursor[MAX_N];
__device__ __align__(16) int    d_col[MAX_E];
__device__ __align__(16) float  d_wgt[MAX_E];
__device__ __align__(16) float  d_dinv[MAX_N];
__device__ __align__(16) int    d_blocksum[NB1024 + 1];
__device__ __align__(16) float  d_xpad[MAX_N * 8];
__device__ __align__(16) float  d_aggx[MAX_N * 8];
__device__ __align__(16) float  d_buf1[MAX_N * HDIM];
__device__ __align__(16) float  d_buf2[MAX_N * HDIM];
__device__ __align__(16) __half d_hwh[MAX_N * HDIM];
__device__ __align__(16) float  d_psum[MAX_G * HDIM];
__device__ __align__(16) float  d_pcnt[MAX_G];

__device__ __forceinline__ void red_add_v4(float4* addr, float4 v) {
    asm volatile("red.global.add.v4.f32 [%0], {%1,%2,%3,%4};"
                 :: "l"(addr), "f"(v.x), "f"(v.y), "f"(v.z), "f"(v.w)
                 : "memory");
}

// ---------------- prep ----------------
__global__ void zero_kernel(int* cnt, float* psum, float* pcnt, int n, int g) {
    int i = blockIdx.x * blockDim.x + threadIdx.x;
    if (i < n) cnt[i] = 0;
    if (i < g * HDIM) psum[i] = 0.f;
    if (i < g) pcnt[i] = 0.f;
}

__global__ void count_kernel(const int* __restrict__ dst, int* __restrict__ cnt, int nE) {
    int e = blockIdx.x * blockDim.x + threadIdx.x;
    if (e >= nE) return;
    atomicAdd(&cnt[dst[e]], 1);
}

__global__ void count_batch_kernel(const int* __restrict__ batch, float* __restrict__ pcnt, int n) {
    int i = blockIdx.x * blockDim.x + threadIdx.x;
    if (i >= n) return;
    atomicAdd(&pcnt[batch[i]], 1.f);
}

// phase 1: per-block exclusive scan of cnt -> rowptr(local), block totals; also dinv
__global__ void scan_phase1(const int* __restrict__ cnt, int* __restrict__ rowptr,
                            int* __restrict__ blocksum, float* __restrict__ dinv, int n) {
    __shared__ int ws[32];
    int t = threadIdx.x, lane = t & 31, w = t >> 5;
    int i = blockIdx.x * 1024 + t;
    int v = (i < n) ? cnt[i] : 0;
    if (i < n) dinv[i] = rsqrtf((float)v + 1.0f);
    int incl = v;
#pragma unroll
    for (int o = 1; o < 32; o <<= 1) {
        int x = __shfl_up_sync(0xffffffffu, incl, o);
        if (lane >= o) incl += x;
    }
    if (lane == 31) ws[w] = incl;
    __syncthreads();
    if (w == 0) {
        int x = ws[lane];
        int incl2 = x;
#pragma unroll
        for (int o = 1; o < 32; o <<= 1) {
            int y = __shfl_up_sync(0xffffffffu, incl2, o);
            if (lane >= o) incl2 += y;
        }
        ws[lane] = incl2 - x;
    }
    __syncthreads();
    int excl = incl - v + ws[w];
    if (i < n) rowptr[i] = excl;
    if (t == 1023) blocksum[blockIdx.x] = excl + v;
}

// phase 2: exclusive scan of block sums (single block, <=128 blocks)
__global__ void scan_phase2(int* __restrict__ bs, int m) {
    __shared__ int ws[4];
    int t = threadIdx.x, lane = t & 31, w = t >> 5;
    int v = (t < m) ? bs[t] : 0;
    int incl = v;
#pragma unroll
    for (int o = 1; o < 32; o <<= 1) {
        int x = __shfl_up_sync(0xffffffffu, incl, o);
        if (lane >= o) incl += x;
    }
    if (lane == 31) ws[w] = incl;
    __syncthreads();
    if (t == 0) {
        int s = 0;
#pragma unroll
        for (int q = 0; q < 4; q++) { int x = ws[q]; ws[q] = s; s += x; }
    }
    __syncthreads();
    int excl = incl - v + ws[w];
    if (t < m) bs[t] = excl;
}

// phase 3: add block offsets; init cursor; set rowptr[n]
__global__ void scan_phase3(int* __restrict__ rowptr, int* __restrict__ cursor,
                            const int* __restrict__ bs, int n, int nE) {
    int i = blockIdx.x * 1024 + threadIdx.x;
    int off = bs[blockIdx.x];
    if (i < n) { int r = rowptr[i] + off; rowptr[i] = r; cursor[i] = r; }
    if (blockIdx.x == 0 && threadIdx.x == 0) rowptr[n] = nE;
}

__global__ void scatter_kernel(const int* __restrict__ src, const int* __restrict__ dst,
                               const float* __restrict__ dinv,
                               int* __restrict__ cursor,
                               int* __restrict__ col, float* __restrict__ wgt, int nE) {
    int e = blockIdx.x * blockDim.x + threadIdx.x;
    if (e >= nE) return;
    int s = src[e];
    int d = dst[e];
    int idx = atomicAdd(&cursor[d], 1);
    col[idx] = s;
    wgt[idx] = dinv[s] * dinv[d];
}

// pad x [N,5] -> xpad [N,8]
__global__ void pad_x(const float* __restrict__ x, float* __restrict__ xpad, int n) {
    int i = blockIdx.x * blockDim.x + threadIdx.x;
    if (i >= n * 8) return;
    int node = i >> 3, c = i & 7;
    xpad[i] = (c < 5) ? x[node * 5 + c] : 0.f;
}

// layer-1 aggregation over raw x (8-float padded rows), 2 threads/node
__global__ void aggx_kernel(const int* __restrict__ rowptr,
                            const int* __restrict__ col, const float* __restrict__ wgt,
                            const float* __restrict__ dinv,
                            const float4* __restrict__ xp4, float4* __restrict__ out4, int n) {
    int t = blockIdx.x * blockDim.x + threadIdx.x;
    int node = t >> 1;
    int j = t & 1;
    if (node >= n) return;
    int beg = rowptr[node];
    int end = rowptr[node + 1];
    float di = dinv[node];
    float sn = di * di;
    float4 self = xp4[(size_t)node * 2 + j];
    float4 acc = make_float4(self.x * sn, self.y * sn, self.z * sn, self.w * sn);
    int k = beg;
#pragma unroll 1
    for (; k + 4 <= end; k += 4) {
        int c0 = __ldg(&col[k]);     float w0 = __ldg(&wgt[k]);
        int c1 = __ldg(&col[k + 1]); float w1 = __ldg(&wgt[k + 1]);
        int c2 = __ldg(&col[k + 2]); float w2 = __ldg(&wgt[k + 2]);
        int c3 = __ldg(&col[k + 3]); float w3 = __ldg(&wgt[k + 3]);
        float4 v0 = xp4[(size_t)c0 * 2 + j];
        float4 v1 = xp4[(size_t)c1 * 2 + j];
        float4 v2 = xp4[(size_t)c2 * 2 + j];
        float4 v3 = xp4[(size_t)c3 * 2 + j];
        acc.x += w0 * v0.x + w1 * v1.x + w2 * v2.x + w3 * v3.x;
        acc.y += w0 * v0.y + w1 * v1.y + w2 * v2.y + w3 * v3.y;
        acc.z += w0 * v0.z + w1 * v1.z + w2 * v2.z + w3 * v3.z;
        acc.w += w0 * v0.w + w1 * v1.w + w2 * v2.w + w3 * v3.w;
    }
    for (; k < end; k++) {
        int c = __ldg(&col[k]); float w = __ldg(&wgt[k]);
        float4 v = xp4[(size_t)c * 2 + j];
        acc.x += w * v.x; acc.y += w * v.y; acc.z += w * v.z; acc.w += w * v.w;
    }
    out4[(size_t)node * 2 + j] = acc;
}

// layer-1 GEMM on aggregated x + BN + ReLU -> buf1 fp32
__global__ void gemm5_bn(const float* __restrict__ aggx, const float* __restrict__ W,
                         const float* __restrict__ b, const float* __restrict__ g,
                         const float* __restrict__ be, const float* __restrict__ rm,
                         const float* __restrict__ rv,
                         float* __restrict__ out, int n) {
    int i = blockIdx.x * blockDim.x + threadIdx.x;
    if (i >= n * HDIM) return;
    int node = i >> 6, c = i & 63;
    float acc = 0.f;
#pragma unroll
    for (int k = 0; k < 5; k++)
        acc += aggx[node * 8 + k] * W[k * HDIM + c];
    float alpha = g[c] * rsqrtf(rv[c] + 1e-5f);
    float beta = (b[c] - rm[c]) * alpha + be[c];
    out[i] = fmaxf(acc * alpha + beta, 0.f);
}

// 64x64 GEMM fp32 in -> fp16 hw out
__global__ void gemm64h(const float* __restrict__ in, const float* __restrict__ W,
                        __half* __restrict__ hwh, int n) {
    __shared__ float sA[64][65];
    __shared__ __align__(16) float sB[64][64];
    int block_row = blockIdx.x * 64;
    int tid = threadIdx.x;

    for (int i = tid; i < 4096; i += 256)
        sB[i >> 6][i & 63] = W[i];
    for (int i = tid; i < 4096; i += 256) {
        int r = i >> 6, c = i & 63;
        int node = block_row + r;
        sA[r][c] = (node < n) ? in[node * HDIM + c] : 0.f;
    }
    __syncthreads();

    int tr = (tid >> 4) * 4;
    int tc = (tid & 15) * 4;
    float acc[4][4];
#pragma unroll
    for (int i = 0; i < 4; i++)
#pragma unroll
        for (int j = 0; j < 4; j++) acc[i][j] = 0.f;

#pragma unroll 8
    for (int k = 0; k < 64; k++) {
        float a0 = sA[tr + 0][k];
        float a1 = sA[tr + 1][k];
        float a2 = sA[tr + 2][k];
        float a3 = sA[tr + 3][k];
        float4 b = *reinterpret_cast<const float4*>(&sB[k][tc]);
        acc[0][0] += a0 * b.x; acc[0][1] += a0 * b.y; acc[0][2] += a0 * b.z; acc[0][3] += a0 * b.w;
        acc[1][0] += a1 * b.x; acc[1][1] += a1 * b.y; acc[1][2] += a1 * b.z; acc[1][3] += a1 * b.w;
        acc[2][0] += a2 * b.x; acc[2][1] += a2 * b.y; acc[2][2] += a2 * b.z; acc[2][3] += a2 * b.w;
        acc[3][0] += a3 * b.x; acc[3][1] += a3 * b.y; acc[3][2] += a3 * b.z; acc[3][3] += a3 * b.w;
    }

#pragma unroll
    for (int i = 0; i < 4; i++) {
        int node = block_row + tr + i;
        if (node >= n) break;
        __half2* hp = reinterpret_cast<__half2*>(hwh + (size_t)node * HDIM + tc);
        hp[0] = __floats2half2_rn(acc[i][0], acc[i][1]);
        hp[1] = __floats2half2_rn(acc[i][2], acc[i][3]);
    }
}

// fused CSR aggregation (fp16 gather, fp32 accum) + bias + BN + ReLU (+pool)
template <bool POOL>
__global__ void agg_fused_h(const int* __restrict__ rowptr,
                            const int* __restrict__ col, const float* __restrict__ wgt,
                            const float* __restrict__ dinv,
                            const uint2* __restrict__ hw2,
                            float4* __restrict__ out4,
                            const float* __restrict__ b, const float* __restrict__ g,
                            const float* __restrict__ be, const float* __restrict__ rm,
                            const float* __restrict__ rv,
                            const int* __restrict__ batch, float4* __restrict__ psum4,
                            int n) {
    int t = blockIdx.x * blockDim.x + threadIdx.x;
    int node = t >> 4;
    int j = t & 15;
    if (node >= n) return;

    int beg = rowptr[node];
    int end = rowptr[node + 1];

    float di = dinv[node];
    float sn = di * di;

    float4 acc;
    {
        uint2 raw = hw2[(size_t)node * 16 + j];
        __half2 h0 = *reinterpret_cast<__half2*>(&raw.x);
        __half2 h1 = *reinterpret_cast<__half2*>(&raw.y);
        float2 f0 = __half22float2(h0), f1 = __half22float2(h1);
        acc = make_float4(f0.x * sn, f0.y * sn, f1.x * sn, f1.y * sn);
    }

    int k = beg;
#pragma unroll 1
    for (; k + 4 <= end; k += 4) {
        int c0 = __ldg(&col[k]);     float w0 = __ldg(&wgt[k]);
        int c1 = __ldg(&col[k + 1]); float w1 = __ldg(&wgt[k + 1]);
        int c2 = __ldg(&col[k + 2]); float w2 = __ldg(&wgt[k + 2]);
        int c3 = __ldg(&col[k + 3]); float w3 = __ldg(&wgt[k + 3]);
        uint2 r0 = hw2[(size_t)c0 * 16 + j];
        uint2 r1 = hw2[(size_t)c1 * 16 + j];
        uint2 r2 = hw2[(size_t)c2 * 16 + j];
        uint2 r3 = hw2[(size_t)c3 * 16 + j];
        float2 a0 = __half22float2(*reinterpret_cast<__half2*>(&r0.x));
        float2 b0 = __half22float2(*reinterpret_cast<__half2*>(&r0.y));
        float2 a1 = __half22float2(*reinterpret_cast<__half2*>(&r1.x));
        float2 b1_ = __half22float2(*reinterpret_cast<__half2*>(&r1.y));
        float2 a2 = __half22float2(*reinterpret_cast<__half2*>(&r2.x));
        float2 b2_ = __half22float2(*reinterpret_cast<__half2*>(&r2.y));
        float2 a3 = __half22float2(*reinterpret_cast<__half2*>(&r3.x));
        float2 b3_ = __half22float2(*reinterpret_cast<__half2*>(&r3.y));
        acc.x += w0 * a0.x + w1 * a1.x + w2 * a2.x + w3 * a3.x;
        acc.y += w0 * a0.y + w1 * a1.y + w2 * a2.y + w3 * a3.y;
        acc.z += w0 * b0.x + w1 * b1_.x + w2 * b2_.x + w3 * b3_.x;
        acc.w += w0 * b0.y + w1 * b1_.y + w2 * b2_.y + w3 * b3_.y;
    }
    for (; k < end; k++) {
        int c = __ldg(&col[k]); float w = __ldg(&wgt[k]);
        uint2 r = hw2[(size_t)c * 16 + j];
        float2 a = __half22float2(*reinterpret_cast<__half2*>(&r.x));
        float2 bb = __half22float2(*reinterpret_cast<__half2*>(&r.y));
        acc.x += w * a.x; acc.y += w * a.y; acc.z += w * bb.x; acc.w += w * bb.y;
    }

    int cb = j * 4;
    float o[4];
    float in[4] = {acc.x, acc.y, acc.z, acc.w};
#pragma unroll
    for (int q = 0; q < 4; q++) {
        int c = cb + q;
        float alpha = g[c] * rsqrtf(rv[c] + 1e-5f);
        float beta = (b[c] - rm[c]) * alpha + be[c];
        o[q] = fmaxf(in[q] * alpha + beta, 0.f);
    }
    float4 h = make_float4(o[0], o[1], o[2], o[3]);

    if (POOL) {
        int gg = batch[node];
        red_add_v4(&psum4[gg * 16 + j], h);
    } else {
        out4[(size_t)node * 16 + j] = h;
    }
}

// ---------------- final MLP ----------------
__global__ void mlp_kernel(const float* __restrict__ psum, const float* __restrict__ pcnt,
                           const float* __restrict__ Wf1, const float* __restrict__ bf1,
                           const float* __restrict__ Wf2, const float* __restrict__ bf2,
                           float* __restrict__ out) {
    int g = blockIdx.x;
    int t = threadIdx.x;  // 0..31
    __shared__ float p[64];
    __shared__ float hh[32];
    float cnt = fmaxf(pcnt[g], 1.f);
    float inv = 1.f / cnt;
    p[t] = psum[g * HDIM + t] * inv;
    p[t + 32] = psum[g * HDIM + t + 32] * inv;
    __syncwarp();
    float acc = bf1[t];
#pragma unroll
    for (int k = 0; k < 64; k++)
        acc += p[k] * Wf1[k * 32 + t];
    hh[t] = fmaxf(acc, 0.f);
    __syncwarp();
    if (t < 2) {
        float o = bf2[t];
#pragma unroll
        for (int k = 0; k < 32; k++)
            o += hh[k] * Wf2[k * 2 + t];
        out[g * 2 + t] = 1.f / (1.f + expf(-o));
    }
}

// ---------------- launch ----------------
extern "C" void kernel_launch(void* const* d_in, const int* in_sizes, int n_in,
                              void* d_out, int out_size) {
    const float* x     = (const float*)d_in[0];
    const int*   ei    = (const int*)d_in[1];
    const int*   batch = (const int*)d_in[2];
    const float* W1 = (const float*)d_in[3];
    const float* b1 = (const float*)d_in[4];
    const float* g1 = (const float*)d_in[5];
    const float* be1 = (const float*)d_in[6];
    const float* rm1 = (const float*)d_in[7];
    const float* rv1 = (const float*)d_in[8];
    const float* W2 = (const float*)d_in[9];
    const float* b2 = (const float*)d_in[10];
    const float* g2 = (const float*)d_in[11];
    const float* be2 = (const float*)d_in[12];
    const float* rm2 = (const float*)d_in[13];
    const float* rv2 = (const float*)d_in[14];
    const float* W3 = (const float*)d_in[15];
    const float* b3 = (const float*)d_in[16];
    const float* g3 = (const float*)d_in[17];
    const float* be3 = (const float*)d_in[18];
    const float* rm3 = (const float*)d_in[19];
    const float* rv3 = (const float*)d_in[20];
    const float* Wf1 = (const float*)d_in[21];
    const float* bf1 = (const float*)d_in[22];
    const float* Wf2 = (const float*)d_in[23];
    const float* bf2 = (const float*)d_in[24];

    int n = in_sizes[0] / 5;
    int e = in_sizes[1] / 2;
    int g = out_size / 2;

    const int* srcp = ei;
    const int* dstp = ei + e;

    int *cnt, *rowptr, *cursor, *colp, *bsum;
    float *wgtp, *dinv, *xpad, *aggx, *buf1, *buf2, *psum, *pcnt;
    __half* hwh;
    cudaGetSymbolAddress((void**)&cnt, d_cnt);
    cudaGetSymbolAddress((void**)&rowptr, d_rowptr);
    cudaGetSymbolAddress((void**)&cursor, d_cursor);
    cudaGetSymbolAddress((void**)&colp, d_col);
    cudaGetSymbolAddress((void**)&bsum, d_blocksum);
    cudaGetSymbolAddress((void**)&wgtp, d_wgt);
    cudaGetSymbolAddress((void**)&dinv, d_dinv);
    cudaGetSymbolAddress((void**)&xpad, d_xpad);
    cudaGetSymbolAddress((void**)&aggx, d_aggx);
    cudaGetSymbolAddress((void**)&buf1, d_buf1);
    cudaGetSymbolAddress((void**)&buf2, d_buf2);
    cudaGetSymbolAddress((void**)&hwh, d_hwh);
    cudaGetSymbolAddress((void**)&psum, d_psum);
    cudaGetSymbolAddress((void**)&pcnt, d_pcnt);

    const int BS = 256;
    int nb1024 = (n + 1023) / 1024;
    int zero_elems = n > g * HDIM ? n : g * HDIM;

    zero_kernel<<<(zero_elems + BS - 1) / BS, BS>>>(cnt, psum, pcnt, n, g);
    count_kernel<<<(e + BS - 1) / BS, BS>>>(dstp, cnt, e);
    count_batch_kernel<<<(n + BS - 1) / BS, BS>>>(batch, pcnt, n);
    scan_phase1<<<nb1024, 1024>>>(cnt, rowptr, bsum, dinv, n);
    scan_phase2<<<1, 128>>>(bsum, nb1024);
    scan_phase3<<<nb1024, 1024>>>(rowptr, cursor, bsum, n, e);
    scatter_kernel<<<(e + BS - 1) / BS, BS>>>(srcp, dstp, dinv, cursor, colp, wgtp, e);
    pad_x<<<(n * 8 + BS - 1) / BS, BS>>>(x, xpad, n);

    int ng16 = (n * 16 + BS - 1) / BS;
    int ng2 = (n * 2 + BS - 1) / BS;

    // layer 1: aggregate raw x (5ch), then GEMM+BN+ReLU -> buf1
    aggx_kernel<<<ng2, BS>>>(rowptr, colp, wgtp, dinv, (const float4*)xpad, (float4*)aggx, n);
    gemm5_bn<<<(n * HDIM + BS - 1) / BS, BS>>>(aggx, W1, b1, g1, be1, rm1, rv1, buf1, n);

    // layer 2: gemm (fp16 out) + fused agg -> buf2
    gemm64h<<<(n + 63) / 64, BS>>>(buf1, W2, hwh, n);
    agg_fused_h<false><<<ng16, BS>>>(rowptr, colp, wgtp, dinv, (const uint2*)hwh,
                                     (float4*)buf2, b2, g2, be2, rm2, rv2,
                                     batch, (float4*)psum, n);
    // layer 3: gemm (fp16 out) + fused agg + pool
    gemm64h<<<(n + 63) / 64, BS>>>(buf2, W3, hwh, n);
    agg_fused_h<true><<<ng16, BS>>>(rowptr, colp, wgtp, dinv, (const uint2*)hwh,
                                    (float4*)buf1, b3, g3, be3, rm3, rv3,
                                    batch, (float4*)psum, n);

    mlp_kernel<<<g, 32>>>(psum, pcnt, Wf1, bf1, Wf2, bf2, (float*)d_out);
}

// round 6
// speedup vs baseline: 2.2417x; 1.0238x over previous
#include <cuda_runtime.h>
#include <cuda_fp16.h>
#include <math.h>

#define MAX_N 100000
#define MAX_E 3200000
#define MAX_G 256
#define HDIM 64
#define NB1024 ((MAX_N + 1023) / 1024)

// ---------------- device scratch ----------------
__device__ __align__(16) int    d_cnt[MAX_N];
__device__ __align__(16) int    d_rowptr[MAX_N + 1];
__device__ __align__(16) int    d_cursor[MAX_N];
__device__ __align__(16) int    d_col[MAX_E];
__device__ __align__(16) float  d_dinv[MAX_N];
__device__ __align__(16) int    d_blocksum[NB1024 + 1];
__device__ __align__(16) float  d_xpad[MAX_N * 8];
__device__ __align__(16) float  d_aggx[MAX_N * 8];
__device__ __align__(16) __half d_hwA[MAX_N * HDIM];
__device__ __align__(16) __half d_hwB[MAX_N * HDIM];
__device__ __align__(16) float  d_psum[MAX_G * HDIM];
__device__ __align__(16) float  d_pcnt[MAX_G];

__device__ __forceinline__ void red_add_v4(float4* addr, float4 v) {
    asm volatile("red.global.add.v4.f32 [%0], {%1,%2,%3,%4};"
                 :: "l"(addr), "f"(v.x), "f"(v.y), "f"(v.z), "f"(v.w)
                 : "memory");
}

// ---------------- prep ----------------
__global__ void zero_kernel(int* cnt, float* psum, float* pcnt, int n, int g) {
    int i = blockIdx.x * blockDim.x + threadIdx.x;
    if (i < n) cnt[i] = 0;
    if (i < g * HDIM) psum[i] = 0.f;
    if (i < g) pcnt[i] = 0.f;
}

// dst in-degree counting + graph node counting in one pass
__global__ void count_kernel(const int* __restrict__ dst, const int* __restrict__ batch,
                             int* __restrict__ cnt, float* __restrict__ pcnt,
                             int nE, int n) {
    int i = blockIdx.x * blockDim.x + threadIdx.x;
    if (i < nE) atomicAdd(&cnt[dst[i]], 1);
    if (i < n) atomicAdd(&pcnt[batch[i]], 1.f);
}

// phase 1: per-block exclusive scan of cnt; also dinv
__global__ void scan_phase1(const int* __restrict__ cnt, int* __restrict__ rowptr,
                            int* __restrict__ blocksum, float* __restrict__ dinv, int n) {
    __shared__ int ws[32];
    int t = threadIdx.x, lane = t & 31, w = t >> 5;
    int i = blockIdx.x * 1024 + t;
    int v = (i < n) ? cnt[i] : 0;
    if (i < n) dinv[i] = rsqrtf((float)v + 1.0f);
    int incl = v;
#pragma unroll
    for (int o = 1; o < 32; o <<= 1) {
        int x = __shfl_up_sync(0xffffffffu, incl, o);
        if (lane >= o) incl += x;
    }
    if (lane == 31) ws[w] = incl;
    __syncthreads();
    if (w == 0) {
        int x = ws[lane];
        int incl2 = x;
#pragma unroll
        for (int o = 1; o < 32; o <<= 1) {
            int y = __shfl_up_sync(0xffffffffu, incl2, o);
            if (lane >= o) incl2 += y;
        }
        ws[lane] = incl2 - x;
    }
    __syncthreads();
    int excl = incl - v + ws[w];
    if (i < n) rowptr[i] = excl;
    if (t == 1023) blocksum[blockIdx.x] = excl + v;
}

__global__ void scan_phase2(int* __restrict__ bs, int m) {
    __shared__ int ws[4];
    int t = threadIdx.x, lane = t & 31, w = t >> 5;
    int v = (t < m) ? bs[t] : 0;
    int incl = v;
#pragma unroll
    for (int o = 1; o < 32; o <<= 1) {
        int x = __shfl_up_sync(0xffffffffu, incl, o);
        if (lane >= o) incl += x;
    }
    if (lane == 31) ws[w] = incl;
    __syncthreads();
    if (t == 0) {
        int s = 0;
#pragma unroll
        for (int q = 0; q < 4; q++) { int x = ws[q]; ws[q] = s; s += x; }
    }
    __syncthreads();
    int excl = incl - v + ws[w];
    if (t < m) bs[t] = excl;
}

__global__ void scan_phase3(int* __restrict__ rowptr, int* __restrict__ cursor,
                            const int* __restrict__ bs, int n, int nE) {
    int i = blockIdx.x * 1024 + threadIdx.x;
    int off = bs[blockIdx.x];
    if (i < n) { int r = rowptr[i] + off; rowptr[i] = r; cursor[i] = r; }
    if (blockIdx.x == 0 && threadIdx.x == 0) rowptr[n] = nE;
}

// scatter: column indices only (weights are algebraically eliminated)
__global__ void scatter_kernel(const int* __restrict__ src, const int* __restrict__ dst,
                               int* __restrict__ cursor, int* __restrict__ col, int nE) {
    int e = blockIdx.x * blockDim.x + threadIdx.x;
    if (e >= nE) return;
    int idx = atomicAdd(&cursor[dst[e]], 1);
    col[idx] = src[e];
}

// xpad[node] = x[node] * dinv[node], padded [N,8]
__global__ void pad_scale_x(const float* __restrict__ x, const float* __restrict__ dinv,
                            float* __restrict__ xpad, int n) {
    int i = blockIdx.x * blockDim.x + threadIdx.x;
    if (i >= n * 8) return;
    int node = i >> 3, c = i & 7;
    xpad[i] = (c < 5) ? x[node * 5 + c] * dinv[node] : 0.f;
}

// layer-1 aggregation: aggx_v = dinv_v * (sum xpad'[col] + xpad'_v); 2 thr/node
__global__ void aggx_kernel(const int* __restrict__ rowptr, const int* __restrict__ col,
                            const float* __restrict__ dinv,
                            const float4* __restrict__ xp4, float4* __restrict__ out4, int n) {
    int t = blockIdx.x * blockDim.x + threadIdx.x;
    int node = t >> 1;
    int j = t & 1;
    if (node >= n) return;
    int beg = rowptr[node], end = rowptr[node + 1];
    float4 acc = xp4[(size_t)node * 2 + j];   // self term (already dinv-scaled)
    int k = beg;
#pragma unroll 1
    for (; k + 4 <= end; k += 4) {
        int c0 = __ldg(&col[k]);     int c1 = __ldg(&col[k + 1]);
        int c2 = __ldg(&col[k + 2]); int c3 = __ldg(&col[k + 3]);
        float4 v0 = xp4[(size_t)c0 * 2 + j];
        float4 v1 = xp4[(size_t)c1 * 2 + j];
        float4 v2 = xp4[(size_t)c2 * 2 + j];
        float4 v3 = xp4[(size_t)c3 * 2 + j];
        acc.x += v0.x + v1.x + v2.x + v3.x;
        acc.y += v0.y + v1.y + v2.y + v3.y;
        acc.z += v0.z + v1.z + v2.z + v3.z;
        acc.w += v0.w + v1.w + v2.w + v3.w;
    }
    for (; k < end; k++) {
        int c = __ldg(&col[k]);
        float4 v = xp4[(size_t)c * 2 + j];
        acc.x += v.x; acc.y += v.y; acc.z += v.z; acc.w += v.w;
    }
    float dv = dinv[node];
    out4[(size_t)node * 2 + j] = make_float4(acc.x * dv, acc.y * dv, acc.z * dv, acc.w * dv);
}

// layer-1 dense chain: h1 = relu(bn1(aggx@W1+b1)); hwA = (h1@W2)*dinv  (fp16)
__global__ __launch_bounds__(256) void l1_fused(
    const float* __restrict__ aggx, const float* __restrict__ W1,
    const float* __restrict__ b1, const float* __restrict__ g1,
    const float* __restrict__ be1, const float* __restrict__ rm1,
    const float* __restrict__ rv1,
    const float* __restrict__ W2, const float* __restrict__ dinv,
    __half* __restrict__ hw, int n) {
    __shared__ float sW1[5][64];
    __shared__ float alphaS[64], betaS[64];
    __shared__ float sA[64][65];
    __shared__ __align__(16) float sW2[64][64];
    int tid = threadIdx.x;
    int bb = blockIdx.x * 64;

    for (int i = tid; i < 320; i += 256) sW1[i >> 6][i & 63] = W1[i];
    for (int i = tid; i < 4096; i += 256) sW2[i >> 6][i & 63] = W2[i];
    if (tid < 64) {
        float alpha = g1[tid] * rsqrtf(rv1[tid] + 1e-5f);
        alphaS[tid] = alpha;
        betaS[tid] = (b1[tid] - rm1[tid]) * alpha + be1[tid];
    }
    __syncthreads();

    {
        int r = tid >> 2, q = tid & 3;
        int node = bb + r;
        float a0 = 0, a1 = 0, a2 = 0, a3 = 0, a4 = 0;
        if (node < n) {
            const float* ar = aggx + (size_t)node * 8;
            a0 = ar[0]; a1 = ar[1]; a2 = ar[2]; a3 = ar[3]; a4 = ar[4];
        }
#pragma unroll
        for (int q2 = 0; q2 < 16; q2++) {
            int c = q * 16 + q2;
            float acc = a0 * sW1[0][c] + a1 * sW1[1][c] + a2 * sW1[2][c]
                      + a3 * sW1[3][c] + a4 * sW1[4][c];
            sA[r][c] = (node < n) ? fmaxf(acc * alphaS[c] + betaS[c], 0.f) : 0.f;
        }
    }
    __syncthreads();

    int tr = (tid >> 4) * 4;
    int tc = (tid & 15) * 4;
    float acc[4][4];
#pragma unroll
    for (int i = 0; i < 4; i++)
#pragma unroll
        for (int j = 0; j < 4; j++) acc[i][j] = 0.f;
#pragma unroll 8
    for (int k = 0; k < 64; k++) {
        float a0 = sA[tr + 0][k], a1 = sA[tr + 1][k], a2 = sA[tr + 2][k], a3 = sA[tr + 3][k];
        float4 b = *reinterpret_cast<const float4*>(&sW2[k][tc]);
        acc[0][0] += a0 * b.x; acc[0][1] += a0 * b.y; acc[0][2] += a0 * b.z; acc[0][3] += a0 * b.w;
        acc[1][0] += a1 * b.x; acc[1][1] += a1 * b.y; acc[1][2] += a1 * b.z; acc[1][3] += a1 * b.w;
        acc[2][0] += a2 * b.x; acc[2][1] += a2 * b.y; acc[2][2] += a2 * b.z; acc[2][3] += a2 * b.w;
        acc[3][0] += a3 * b.x; acc[3][1] += a3 * b.y; acc[3][2] += a3 * b.z; acc[3][3] += a3 * b.w;
    }
#pragma unroll
    for (int i = 0; i < 4; i++) {
        int node = bb + tr + i;
        if (node >= n) break;
        float dv = dinv[node];
        __half2* hp = reinterpret_cast<__half2*>(hw + (size_t)node * HDIM + tc);
        hp[0] = __floats2half2_rn(acc[i][0] * dv, acc[i][1] * dv);
        hp[1] = __floats2half2_rn(acc[i][2] * dv, acc[i][3] * dv);
    }
}

// fused: aggregate hw_in (fp16, dinv-scaled), BN+ReLU, then @W_next, *dinv -> hw_out fp16
// block = 32 nodes, 8 threads/node (each thread: 8 channels)
__global__ __launch_bounds__(256) void agg_gemm(
    const int* __restrict__ rowptr, const int* __restrict__ col,
    const float* __restrict__ dinv, const uint2* __restrict__ hw2,
    const float* __restrict__ b, const float* __restrict__ g,
    const float* __restrict__ be, const float* __restrict__ rm,
    const float* __restrict__ rv,
    const float* __restrict__ W, __half* __restrict__ hw_out, int n) {
    __shared__ float alphaS[64], betaS[64];
    __shared__ float sA[32][65];
    __shared__ __align__(16) float sW[64][64];
    int tid = threadIdx.x;
    int bb = blockIdx.x * 32;

    for (int i = tid; i < 4096; i += 256) sW[i >> 6][i & 63] = W[i];
    if (tid < 64) {
        float alpha = g[tid] * rsqrtf(rv[tid] + 1e-5f);
        alphaS[tid] = alpha;
        betaS[tid] = (b[tid] - rm[tid]) * alpha + be[tid];
    }
    __syncthreads();

    {
        int r = tid >> 3, j = tid & 7;
        int node = bb + r;
        float acc[8] = {0, 0, 0, 0, 0, 0, 0, 0};
        float dv = 0.f;
        if (node < n) {
            size_t base = (size_t)node * 16 + j * 2;
            uint2 s0 = hw2[base], s1 = hw2[base + 1];
            float2 f0 = __half22float2(*reinterpret_cast<__half2*>(&s0.x));
            float2 f1 = __half22float2(*reinterpret_cast<__half2*>(&s0.y));
            float2 f2 = __half22float2(*reinterpret_cast<__half2*>(&s1.x));
            float2 f3 = __half22float2(*reinterpret_cast<__half2*>(&s1.y));
            acc[0] = f0.x; acc[1] = f0.y; acc[2] = f1.x; acc[3] = f1.y;
            acc[4] = f2.x; acc[5] = f2.y; acc[6] = f3.x; acc[7] = f3.y;
            int beg = rowptr[node], end = rowptr[node + 1];
            int k = beg;
#pragma unroll 1
            for (; k + 2 <= end; k += 2) {
                int c0 = __ldg(&col[k]);
                int c1 = __ldg(&col[k + 1]);
                size_t b0 = (size_t)c0 * 16 + j * 2;
                size_t b1 = (size_t)c1 * 16 + j * 2;
                uint2 u00 = hw2[b0], u01 = hw2[b0 + 1];
                uint2 u10 = hw2[b1], u11 = hw2[b1 + 1];
                float2 p0 = __half22float2(*reinterpret_cast<__half2*>(&u00.x));
                float2 p1 = __half22float2(*reinterpret_cast<__half2*>(&u00.y));
                float2 p2 = __half22float2(*reinterpret_cast<__half2*>(&u01.x));
                float2 p3 = __half22float2(*reinterpret_cast<__half2*>(&u01.y));
                float2 q0 = __half22float2(*reinterpret_cast<__half2*>(&u10.x));
                float2 q1 = __half22float2(*reinterpret_cast<__half2*>(&u10.y));
                float2 q2 = __half22float2(*reinterpret_cast<__half2*>(&u11.x));
                float2 q3 = __half22float2(*reinterpret_cast<__half2*>(&u11.y));
                acc[0] += p0.x + q0.x; acc[1] += p0.y + q0.y;
                acc[2] += p1.x + q1.x; acc[3] += p1.y + q1.y;
                acc[4] += p2.x + q2.x; acc[5] += p2.y + q2.y;
                acc[6] += p3.x + q3.x; acc[7] += p3.y + q3.y;
            }
            for (; k < end; k++) {
                int c = __ldg(&col[k]);
                size_t bc = (size_t)c * 16 + j * 2;
                uint2 u0 = hw2[bc], u1 = hw2[bc + 1];
                float2 p0 = __half22float2(*reinterpret_cast<__half2*>(&u0.x));
                float2 p1 = __half22float2(*reinterpret_cast<__half2*>(&u0.y));
                float2 p2 = __half22float2(*reinterpret_cast<__half2*>(&u1.x));
                float2 p3 = __half22float2(*reinterpret_cast<__half2*>(&u1.y));
                acc[0] += p0.x; acc[1] += p0.y; acc[2] += p1.x; acc[3] += p1.y;
                acc[4] += p2.x; acc[5] += p2.y; acc[6] += p3.x; acc[7] += p3.y;
            }
            dv = dinv[node];
        }
#pragma unroll
        for (int q = 0; q < 8; q++) {
            int c = j * 8 + q;
            sA[r][c] = (node < n) ? fmaxf(acc[q] * dv * alphaS[c] + betaS[c], 0.f) : 0.f;
        }
    }
    __syncthreads();

    // GEMM 32x64 @ 64x64
    {
        int r2 = tid >> 3;
        int c0 = (tid & 7) * 8;
        float o[8] = {0, 0, 0, 0, 0, 0, 0, 0};
#pragma unroll 8
        for (int k = 0; k < 64; k++) {
            float a = sA[r2][k];
            float4 w0 = *reinterpret_cast<const float4*>(&sW[k][c0]);
            float4 w1 = *reinterpret_cast<const float4*>(&sW[k][c0 + 4]);
            o[0] += a * w0.x; o[1] += a * w0.y; o[2] += a * w0.z; o[3] += a * w0.w;
            o[4] += a * w1.x; o[5] += a * w1.y; o[6] += a * w1.z; o[7] += a * w1.w;
        }
        int node2 = bb + r2;
        if (node2 < n) {
            float dv2 = dinv[node2];
            __half2* hp = reinterpret_cast<__half2*>(hw_out + (size_t)node2 * HDIM + c0);
            hp[0] = __floats2half2_rn(o[0] * dv2, o[1] * dv2);
            hp[1] = __floats2half2_rn(o[2] * dv2, o[3] * dv2);
            hp[2] = __floats2half2_rn(o[4] * dv2, o[5] * dv2);
            hp[3] = __floats2half2_rn(o[6] * dv2, o[7] * dv2);
        }
    }
}

// layer-3: aggregate + BN + ReLU + pool (16 thr/node)
__global__ void agg_pool(const int* __restrict__ rowptr, const int* __restrict__ col,
                         const float* __restrict__ dinv, const uint2* __restrict__ hw2,
                         const float* __restrict__ b, const float* __restrict__ g,
                         const float* __restrict__ be, const float* __restrict__ rm,
                         const float* __restrict__ rv,
                         const int* __restrict__ batch, float4* __restrict__ psum4, int n) {
    int t = blockIdx.x * blockDim.x + threadIdx.x;
    int node = t >> 4;
    int j = t & 15;
    if (node >= n) return;
    int beg = rowptr[node], end = rowptr[node + 1];

    float4 acc;
    {
        uint2 raw = hw2[(size_t)node * 16 + j];
        float2 f0 = __half22float2(*reinterpret_cast<__half2*>(&raw.x));
        float2 f1 = __half22float2(*reinterpret_cast<__half2*>(&raw.y));
        acc = make_float4(f0.x, f0.y, f1.x, f1.y);
    }
    int k = beg;
#pragma unroll 1
    for (; k + 4 <= end; k += 4) {
        int c0 = __ldg(&col[k]);     int c1 = __ldg(&col[k + 1]);
        int c2 = __ldg(&col[k + 2]); int c3 = __ldg(&col[k + 3]);
        uint2 r0 = hw2[(size_t)c0 * 16 + j];
        uint2 r1 = hw2[(size_t)c1 * 16 + j];
        uint2 r2 = hw2[(size_t)c2 * 16 + j];
        uint2 r3 = hw2[(size_t)c3 * 16 + j];
        float2 a0 = __half22float2(*reinterpret_cast<__half2*>(&r0.x));
        float2 b0 = __half22float2(*reinterpret_cast<__half2*>(&r0.y));
        float2 a1 = __half22float2(*reinterpret_cast<__half2*>(&r1.x));
        float2 b1_ = __half22float2(*reinterpret_cast<__half2*>(&r1.y));
        float2 a2 = __half22float2(*reinterpret_cast<__half2*>(&r2.x));
        float2 b2_ = __half22float2(*reinterpret_cast<__half2*>(&r2.y));
        float2 a3 = __half22float2(*reinterpret_cast<__half2*>(&r3.x));
        float2 b3_ = __half22float2(*reinterpret_cast<__half2*>(&r3.y));
        acc.x += a0.x + a1.x + a2.x + a3.x;
        acc.y += a0.y + a1.y + a2.y + a3.y;
        acc.z += b0.x + b1_.x + b2_.x + b3_.x;
        acc.w += b0.y + b1_.y + b2_.y + b3_.y;
    }
    for (; k < end; k++) {
        int c = __ldg(&col[k]);
        uint2 r = hw2[(size_t)c * 16 + j];
        float2 a = __half22float2(*reinterpret_cast<__half2*>(&r.x));
        float2 bb = __half22float2(*reinterpret_cast<__half2*>(&r.y));
        acc.x += a.x; acc.y += a.y; acc.z += bb.x; acc.w += bb.y;
    }
    float dv = dinv[node];
    int cb = j * 4;
    float o[4];
    float in[4] = {acc.x * dv, acc.y * dv, acc.z * dv, acc.w * dv};
#pragma unroll
    for (int q = 0; q < 4; q++) {
        int c = cb + q;
        float alpha = g[c] * rsqrtf(rv[c] + 1e-5f);
        float beta = (b[c] - rm[c]) * alpha + be[c];
        o[q] = fmaxf(in[q] * alpha + beta, 0.f);
    }
    int gg = batch[node];
    red_add_v4(&psum4[gg * 16 + j], make_float4(o[0], o[1], o[2], o[3]));
}

// ---------------- final MLP ----------------
__global__ void mlp_kernel(const float* __restrict__ psum, const float* __restrict__ pcnt,
                           const float* __restrict__ Wf1, const float* __restrict__ bf1,
                           const float* __restrict__ Wf2, const float* __restrict__ bf2,
                           float* __restrict__ out) {
    int g = blockIdx.x;
    int t = threadIdx.x;
    __shared__ float p[64];
    __shared__ float hh[32];
    float cnt = fmaxf(pcnt[g], 1.f);
    float inv = 1.f / cnt;
    p[t] = psum[g * HDIM + t] * inv;
    p[t + 32] = psum[g * HDIM + t + 32] * inv;
    __syncwarp();
    float acc = bf1[t];
#pragma unroll
    for (int k = 0; k < 64; k++)
        acc += p[k] * Wf1[k * 32 + t];
    hh[t] = fmaxf(acc, 0.f);
    __syncwarp();
    if (t < 2) {
        float o = bf2[t];
#pragma unroll
        for (int k = 0; k < 32; k++)
            o += hh[k] * Wf2[k * 2 + t];
        out[g * 2 + t] = 1.f / (1.f + expf(-o));
    }
}

// ---------------- launch ----------------
extern "C" void kernel_launch(void* const* d_in, const int* in_sizes, int n_in,
                              void* d_out, int out_size) {
    const float* x     = (const float*)d_in[0];
    const int*   ei    = (const int*)d_in[1];
    const int*   batch = (const int*)d_in[2];
    const float* W1 = (const float*)d_in[3];
    const float* b1 = (const float*)d_in[4];
    const float* g1 = (const float*)d_in[5];
    const float* be1 = (const float*)d_in[6];
    const float* rm1 = (const float*)d_in[7];
    const float* rv1 = (const float*)d_in[8];
    const float* W2 = (const float*)d_in[9];
    const float* b2 = (const float*)d_in[10];
    const float* g2 = (const float*)d_in[11];
    const float* be2 = (const float*)d_in[12];
    const float* rm2 = (const float*)d_in[13];
    const float* rv2 = (const float*)d_in[14];
    const float* W3 = (const float*)d_in[15];
    const float* b3 = (const float*)d_in[16];
    const float* g3 = (const float*)d_in[17];
    const float* be3 = (const float*)d_in[18];
    const float* rm3 = (const float*)d_in[19];
    const float* rv3 = (const float*)d_in[20];
    const float* Wf1 = (const float*)d_in[21];
    const float* bf1 = (const float*)d_in[22];
    const float* Wf2 = (const float*)d_in[23];
    const float* bf2 = (const float*)d_in[24];

    int n = in_sizes[0] / 5;
    int e = in_sizes[1] / 2;
    int g = out_size / 2;

    const int* srcp = ei;
    const int* dstp = ei + e;

    int *cnt, *rowptr, *cursor, *colp, *bsum;
    float *dinv, *xpad, *aggx, *psum, *pcnt;
    __half *hwA, *hwB;
    cudaGetSymbolAddress((void**)&cnt, d_cnt);
    cudaGetSymbolAddress((void**)&rowptr, d_rowptr);
    cudaGetSymbolAddress((void**)&cursor, d_cursor);
    cudaGetSymbolAddress((void**)&colp, d_col);
    cudaGetSymbolAddress((void**)&bsum, d_blocksum);
    cudaGetSymbolAddress((void**)&dinv, d_dinv);
    cudaGetSymbolAddress((void**)&xpad, d_xpad);
    cudaGetSymbolAddress((void**)&aggx, d_aggx);
    cudaGetSymbolAddress((void**)&hwA, d_hwA);
    cudaGetSymbolAddress((void**)&hwB, d_hwB);
    cudaGetSymbolAddress((void**)&psum, d_psum);
    cudaGetSymbolAddress((void**)&pcnt, d_pcnt);

    const int BS = 256;
    int nb1024 = (n + 1023) / 1024;
    int zero_elems = n > g * HDIM ? n : g * HDIM;

    zero_kernel<<<(zero_elems + BS - 1) / BS, BS>>>(cnt, psum, pcnt, n, g);
    count_kernel<<<(e + BS - 1) / BS, BS>>>(dstp, batch, cnt, pcnt, e, n);
    scan_phase1<<<nb1024, 1024>>>(cnt, rowptr, bsum, dinv, n);
    scan_phase2<<<1, 128>>>(bsum, nb1024);
    scan_phase3<<<nb1024, 1024>>>(rowptr, cursor, bsum, n, e);
    scatter_kernel<<<(e + BS - 1) / BS, BS>>>(srcp, dstp, cursor, colp, e);
    pad_scale_x<<<(n * 8 + BS - 1) / BS, BS>>>(x, dinv, xpad, n);

    // layer 1: aggregate raw x' then dense chain (W1 + BN1 + ReLU + W2) -> hwA
    aggx_kernel<<<(n * 2 + BS - 1) / BS, BS>>>(rowptr, colp, dinv, (const float4*)xpad,
                                               (float4*)aggx, n);
    l1_fused<<<(n + 63) / 64, 256>>>(aggx, W1, b1, g1, be1, rm1, rv1, W2, dinv, hwA, n);

    // layer 2: agg(hwA) + BN2 + ReLU + W3 -> hwB
    agg_gemm<<<(n + 31) / 32, 256>>>(rowptr, colp, dinv, (const uint2*)hwA,
                                     b2, g2, be2, rm2, rv2, W3, hwB, n);

    // layer 3: agg(hwB) + BN3 + ReLU + pool
    agg_pool<<<(n * 16 + BS - 1) / BS, BS>>>(rowptr, colp, dinv, (const uint2*)hwB,
                                             b3, g3, be3, rm3, rv3,
                                             batch, (float4*)psum, n);

    mlp_kernel<<<g, 32>>>(psum, pcnt, Wf1, bf1, Wf2, bf2, (float*)d_out);
}

// round 8
// speedup vs baseline: 2.2469x; 1.0023x over previous
#include <cuda_runtime.h>
#include <cuda_fp16.h>
#include <math.h>

#define MAX_N 100000
#define MAX_E 3200000
#define MAX_G 256
#define HDIM 64
#define NB1024 ((MAX_N + 1023) / 1024)

// ---------------- device scratch ----------------
__device__ __align__(16) int    d_cnt[MAX_N];
__device__ __align__(16) int    d_rowptr[MAX_N + 1];
__device__ __align__(16) int    d_cursor[MAX_N];
__device__ __align__(16) int    d_col[MAX_E];
__device__ __align__(16) float  d_dinv[MAX_N];
__device__ __align__(16) int    d_blocksum[NB1024 + 1];
__device__ __align__(16) float  d_xpad[MAX_N * 8];
__device__ __align__(16) float  d_aggx[MAX_N * 8];
__device__ __align__(16) __half d_hwA[MAX_N * HDIM];
__device__ __align__(16) __half d_hwB[MAX_N * HDIM];
__device__ __align__(16) float  d_psum[MAX_G * HDIM];
__device__ __align__(16) float  d_pcnt[MAX_G];

__device__ __forceinline__ void red_add_v4(float4* addr, float4 v) {
    asm volatile("red.global.add.v4.f32 [%0], {%1,%2,%3,%4};"
                 :: "l"(addr), "f"(v.x), "f"(v.y), "f"(v.z), "f"(v.w)
                 : "memory");
}

// ---------------- prep ----------------
__global__ void zero_kernel(int* cnt, float* psum, float* pcnt, int n, int g) {
    int i = blockIdx.x * blockDim.x + threadIdx.x;
    if (i < n) cnt[i] = 0;
    if (i < g * HDIM) psum[i] = 0.f;
    if (i < g) pcnt[i] = 0.f;
}

__global__ void count_kernel(const int* __restrict__ dst, const int* __restrict__ batch,
                             int* __restrict__ cnt, float* __restrict__ pcnt,
                             int nE, int n) {
    int i = blockIdx.x * blockDim.x + threadIdx.x;
    if (i < nE) atomicAdd(&cnt[dst[i]], 1);
    if (i < n) atomicAdd(&pcnt[batch[i]], 1.f);
}

// phase 1: per-block exclusive scan of cnt; also dinv and xpad = x*dinv
__global__ void scan_phase1(const int* __restrict__ cnt, int* __restrict__ rowptr,
                            int* __restrict__ blocksum, float* __restrict__ dinv,
                            const float* __restrict__ x, float* __restrict__ xpad, int n) {
    __shared__ int ws[32];
    int t = threadIdx.x, lane = t & 31, w = t >> 5;
    int i = blockIdx.x * 1024 + t;
    int v = (i < n) ? cnt[i] : 0;
    if (i < n) {
        float dv = rsqrtf((float)v + 1.0f);
        dinv[i] = dv;
        const float* xr = x + (size_t)i * 5;
        float4* xp = reinterpret_cast<float4*>(xpad + (size_t)i * 8);
        xp[0] = make_float4(xr[0] * dv, xr[1] * dv, xr[2] * dv, xr[3] * dv);
        xp[1] = make_float4(xr[4] * dv, 0.f, 0.f, 0.f);
    }
    int incl = v;
#pragma unroll
    for (int o = 1; o < 32; o <<= 1) {
        int xx = __shfl_up_sync(0xffffffffu, incl, o);
        if (lane >= o) incl += xx;
    }
    if (lane == 31) ws[w] = incl;
    __syncthreads();
    if (w == 0) {
        int xx = ws[lane];
        int incl2 = xx;
#pragma unroll
        for (int o = 1; o < 32; o <<= 1) {
            int y = __shfl_up_sync(0xffffffffu, incl2, o);
            if (lane >= o) incl2 += y;
        }
        ws[lane] = incl2 - xx;
    }
    __syncthreads();
    int excl = incl - v + ws[w];
    if (i < n) rowptr[i] = excl;
    if (t == 1023) blocksum[blockIdx.x] = excl + v;
}

// phase 3 (phase 2 merged): each block reduces its prefix of blocksums itself
__global__ void scan_phase3(int* __restrict__ rowptr, int* __restrict__ cursor,
                            const int* __restrict__ bs, int n, int nE) {
    __shared__ int s_off;
    int t = threadIdx.x;
    if (t < 32) {
        int s = 0;
        for (int q = t; q < blockIdx.x; q += 32) s += bs[q];
#pragma unroll
        for (int o = 16; o; o >>= 1) s += __shfl_down_sync(0xffffffffu, s, o);
        if (t == 0) s_off = s;
    }
    __syncthreads();
    int i = blockIdx.x * 1024 + t;
    int off = s_off;
    if (i < n) { int r = rowptr[i] + off; rowptr[i] = r; cursor[i] = r; }
    if (blockIdx.x == 0 && t == 0) rowptr[n] = nE;
}

__global__ void scatter_kernel(const int* __restrict__ src, const int* __restrict__ dst,
                               int* __restrict__ cursor, int* __restrict__ col, int nE) {
    int e = blockIdx.x * blockDim.x + threadIdx.x;
    if (e >= nE) return;
    int idx = atomicAdd(&cursor[dst[e]], 1);
    col[idx] = src[e];
}

// layer-1 aggregation over xpad (dinv-prescaled); 2 thr/node, unroll 8
__global__ void aggx_kernel(const int* __restrict__ rowptr, const int* __restrict__ col,
                            const float* __restrict__ dinv,
                            const float4* __restrict__ xp4, float4* __restrict__ out4, int n) {
    int t = blockIdx.x * blockDim.x + threadIdx.x;
    int node = t >> 1;
    int j = t & 1;
    if (node >= n) return;
    int beg = rowptr[node], end = rowptr[node + 1];
    float4 acc = xp4[(size_t)node * 2 + j];
    int k = beg;
#pragma unroll 1
    for (; k + 8 <= end; k += 8) {
        int cc[8];
#pragma unroll
        for (int q = 0; q < 8; q++) cc[q] = __ldg(&col[k + q]);
#pragma unroll
        for (int q = 0; q < 8; q++) {
            float4 v = xp4[(size_t)cc[q] * 2 + j];
            acc.x += v.x; acc.y += v.y; acc.z += v.z; acc.w += v.w;
        }
    }
    for (; k < end; k++) {
        int c = __ldg(&col[k]);
        float4 v = xp4[(size_t)c * 2 + j];
        acc.x += v.x; acc.y += v.y; acc.z += v.z; acc.w += v.w;
    }
    float dv = dinv[node];
    out4[(size_t)node * 2 + j] = make_float4(acc.x * dv, acc.y * dv, acc.z * dv, acc.w * dv);
}

// layer-1 dense chain: h1 = relu(bn1(aggx@W1+b1)); hwA = (h1@W2)*dinv  (fp16)
__global__ __launch_bounds__(256) void l1_fused(
    const float* __restrict__ aggx, const float* __restrict__ W1,
    const float* __restrict__ b1, const float* __restrict__ g1,
    const float* __restrict__ be1, const float* __restrict__ rm1,
    const float* __restrict__ rv1,
    const float* __restrict__ W2, const float* __restrict__ dinv,
    __half* __restrict__ hw, int n) {
    __shared__ float sW1[5][64];
    __shared__ float alphaS[64], betaS[64];
    __shared__ float sA[64][65];
    __shared__ __align__(16) float sW2[64][64];
    int tid = threadIdx.x;
    int bb = blockIdx.x * 64;

    for (int i = tid; i < 320; i += 256) sW1[i >> 6][i & 63] = W1[i];
    for (int i = tid; i < 4096; i += 256) sW2[i >> 6][i & 63] = W2[i];
    if (tid < 64) {
        float alpha = g1[tid] * rsqrtf(rv1[tid] + 1e-5f);
        alphaS[tid] = alpha;
        betaS[tid] = (b1[tid] - rm1[tid]) * alpha + be1[tid];
    }
    __syncthreads();

    {
        int r = tid >> 2, q = tid & 3;
        int node = bb + r;
        float a0 = 0, a1 = 0, a2 = 0, a3 = 0, a4 = 0;
        if (node < n) {
            const float* ar = aggx + (size_t)node * 8;
            a0 = ar[0]; a1 = ar[1]; a2 = ar[2]; a3 = ar[3]; a4 = ar[4];
        }
#pragma unroll
        for (int q2 = 0; q2 < 16; q2++) {
            int c = q * 16 + q2;
            float acc = a0 * sW1[0][c] + a1 * sW1[1][c] + a2 * sW1[2][c]
                      + a3 * sW1[3][c] + a4 * sW1[4][c];
            sA[r][c] = (node < n) ? fmaxf(acc * alphaS[c] + betaS[c], 0.f) : 0.f;
        }
    }
    __syncthreads();

    int tr = (tid >> 4) * 4;
    int tc = (tid & 15) * 4;
    float acc[4][4];
#pragma unroll
    for (int i = 0; i < 4; i++)
#pragma unroll
        for (int j = 0; j < 4; j++) acc[i][j] = 0.f;
#pragma unroll 8
    for (int k = 0; k < 64; k++) {
        float a0 = sA[tr + 0][k], a1 = sA[tr + 1][k], a2 = sA[tr + 2][k], a3 = sA[tr + 3][k];
        float4 b = *reinterpret_cast<const float4*>(&sW2[k][tc]);
        acc[0][0] += a0 * b.x; acc[0][1] += a0 * b.y; acc[0][2] += a0 * b.z; acc[0][3] += a0 * b.w;
        acc[1][0] += a1 * b.x; acc[1][1] += a1 * b.y; acc[1][2] += a1 * b.z; acc[1][3] += a1 * b.w;
        acc[2][0] += a2 * b.x; acc[2][1] += a2 * b.y; acc[2][2] += a2 * b.z; acc[2][3] += a2 * b.w;
        acc[3][0] += a3 * b.x; acc[3][1] += a3 * b.y; acc[3][2] += a3 * b.z; acc[3][3] += a3 * b.w;
    }
#pragma unroll
    for (int i = 0; i < 4; i++) {
        int node = bb + tr + i;
        if (node >= n) break;
        float dv = dinv[node];
        __half2* hp = reinterpret_cast<__half2*>(hw + (size_t)node * HDIM + tc);
        hp[0] = __floats2half2_rn(acc[i][0] * dv, acc[i][1] * dv);
        hp[1] = __floats2half2_rn(acc[i][2] * dv, acc[i][3] * dv);
    }
}

// fused: aggregate hwA (fp16, dinv-scaled), BN+ReLU, @W3, *dinv -> hwB fp16
// 512 threads: 64 nodes/block, 8 thr/node; GROUP-masked shfl broadcast; unroll 4
__global__ __launch_bounds__(512) void agg_gemm(
    const int* __restrict__ rowptr, const int* __restrict__ col,
    const float* __restrict__ dinv, const uint2* __restrict__ hw2,
    const float* __restrict__ b, const float* __restrict__ g,
    const float* __restrict__ be, const float* __restrict__ rm,
    const float* __restrict__ rv,
    const float* __restrict__ W, __half* __restrict__ hw_out, int n) {
    __shared__ float alphaS[64], betaS[64];
    __shared__ float sA[64][65];
    __shared__ __align__(16) float sW[64][64];
    int tid = threadIdx.x;
    int lane = tid & 31;
    int bb = blockIdx.x * 64;

    for (int i = tid; i < 4096; i += 512) sW[i >> 6][i & 63] = W[i];
    if (tid < 64) {
        float alpha = g[tid] * rsqrtf(rv[tid] + 1e-5f);
        alphaS[tid] = alpha;
        betaS[tid] = (b[tid] - rm[tid]) * alpha + be[tid];
    }
    __syncthreads();

    {
        int r = tid >> 3, j = tid & 7;
        int node = bb + r;
        int cn = (node < n) ? node : (n - 1);
        int grp = lane & 24;                       // 8-lane group base within warp
        unsigned gmask = 0xFFu << grp;             // lanes of THIS node only (convergent)
        float acc[8];
        {
            size_t base = (size_t)cn * 16 + j * 2;
            uint2 s0 = hw2[base], s1 = hw2[base + 1];
            float2 f0 = __half22float2(*reinterpret_cast<__half2*>(&s0.x));
            float2 f1 = __half22float2(*reinterpret_cast<__half2*>(&s0.y));
            float2 f2 = __half22float2(*reinterpret_cast<__half2*>(&s1.x));
            float2 f3 = __half22float2(*reinterpret_cast<__half2*>(&s1.y));
            acc[0] = f0.x; acc[1] = f0.y; acc[2] = f1.x; acc[3] = f1.y;
            acc[4] = f2.x; acc[5] = f2.y; acc[6] = f3.x; acc[7] = f3.y;
        }
        int beg = rowptr[cn], end = rowptr[cn + 1];
        int k = beg;
#pragma unroll 1
        for (; k + 4 <= end; k += 4) {
            int cw = __ldg(&col[k + (lane & 3)]);
            uint2 u[8];
#pragma unroll
            for (int q = 0; q < 4; q++) {
                int c = __shfl_sync(gmask, cw, grp | q);
                size_t bc = (size_t)c * 16 + j * 2;
                u[q * 2] = hw2[bc];
                u[q * 2 + 1] = hw2[bc + 1];
            }
#pragma unroll
            for (int q = 0; q < 4; q++) {
                float2 p0 = __half22float2(*reinterpret_cast<__half2*>(&u[q * 2].x));
                float2 p1 = __half22float2(*reinterpret_cast<__half2*>(&u[q * 2].y));
                float2 p2 = __half22float2(*reinterpret_cast<__half2*>(&u[q * 2 + 1].x));
                float2 p3 = __half22float2(*reinterpret_cast<__half2*>(&u[q * 2 + 1].y));
                acc[0] += p0.x; acc[1] += p0.y; acc[2] += p1.x; acc[3] += p1.y;
                acc[4] += p2.x; acc[5] += p2.y; acc[6] += p3.x; acc[7] += p3.y;
            }
        }
        for (; k < end; k++) {
            int c = __ldg(&col[k]);
            size_t bc = (size_t)c * 16 + j * 2;
            uint2 u0 = hw2[bc], u1 = hw2[bc + 1];
            float2 p0 = __half22float2(*reinterpret_cast<__half2*>(&u0.x));
            float2 p1 = __half22float2(*reinterpret_cast<__half2*>(&u0.y));
            float2 p2 = __half22float2(*reinterpret_cast<__half2*>(&u1.x));
            float2 p3 = __half22float2(*reinterpret_cast<__half2*>(&u1.y));
            acc[0] += p0.x; acc[1] += p0.y; acc[2] += p1.x; acc[3] += p1.y;
            acc[4] += p2.x; acc[5] += p2.y; acc[6] += p3.x; acc[7] += p3.y;
        }
        float dv = dinv[cn];
#pragma unroll
        for (int q = 0; q < 8; q++) {
            int c = j * 8 + q;
            sA[r][c] = fmaxf(acc[q] * dv * alphaS[c] + betaS[c], 0.f);
        }
    }
    __syncthreads();

    // GEMM 64x64 @ 64x64, 8 outputs/thread
    {
        int r2 = tid >> 3;
        int c0 = (tid & 7) * 8;
        float o[8] = {0, 0, 0, 0, 0, 0, 0, 0};
#pragma unroll 8
        for (int k = 0; k < 64; k++) {
            float a = sA[r2][k];
            float4 w0 = *reinterpret_cast<const float4*>(&sW[k][c0]);
            float4 w1 = *reinterpret_cast<const float4*>(&sW[k][c0 + 4]);
            o[0] += a * w0.x; o[1] += a * w0.y; o[2] += a * w0.z; o[3] += a * w0.w;
            o[4] += a * w1.x; o[5] += a * w1.y; o[6] += a * w1.z; o[7] += a * w1.w;
        }
        int node2 = bb + r2;
        if (node2 < n) {
            float dv2 = dinv[node2];
            __half2* hp = reinterpret_cast<__half2*>(hw_out + (size_t)node2 * HDIM + c0);
            hp[0] = __floats2half2_rn(o[0] * dv2, o[1] * dv2);
            hp[1] = __floats2half2_rn(o[2] * dv2, o[3] * dv2);
            hp[2] = __floats2half2_rn(o[4] * dv2, o[5] * dv2);
            hp[3] = __floats2half2_rn(o[6] * dv2, o[7] * dv2);
        }
    }
}

// layer-3: aggregate + BN + ReLU + pool; 16 thr/node, GROUP-masked shfl, unroll 8
__global__ void agg_pool(const int* __restrict__ rowptr, const int* __restrict__ col,
                         const float* __restrict__ dinv, const uint2* __restrict__ hw2,
                         const float* __restrict__ b, const float* __restrict__ g,
                         const float* __restrict__ be, const float* __restrict__ rm,
                         const float* __restrict__ rv,
                         const int* __restrict__ batch, float4* __restrict__ psum4, int n) {
    int t = blockIdx.x * blockDim.x + threadIdx.x;
    int node = t >> 4;
    int j = t & 15;
    int lane = threadIdx.x & 31;
    bool valid = (node < n);
    int cn = valid ? node : (n - 1);
    int grp = lane & 16;                       // 16-lane group base within warp
    unsigned gmask = 0xFFFFu << grp;           // lanes of THIS node only (convergent)

    int beg = rowptr[cn], end = rowptr[cn + 1];
    float4 acc;
    {
        uint2 raw = hw2[(size_t)cn * 16 + j];
        float2 f0 = __half22float2(*reinterpret_cast<__half2*>(&raw.x));
        float2 f1 = __half22float2(*reinterpret_cast<__half2*>(&raw.y));
        acc = make_float4(f0.x, f0.y, f1.x, f1.y);
    }
    int k = beg;
#pragma unroll 1
    for (; k + 8 <= end; k += 8) {
        int cw = __ldg(&col[k + (lane & 7)]);
        uint2 u[8];
#pragma unroll
        for (int q = 0; q < 8; q++) {
            int c = __shfl_sync(gmask, cw, grp | q);
            u[q] = hw2[(size_t)c * 16 + j];
        }
#pragma unroll
        for (int q = 0; q < 8; q++) {
            float2 a = __half22float2(*reinterpret_cast<__half2*>(&u[q].x));
            float2 bb = __half22float2(*reinterpret_cast<__half2*>(&u[q].y));
            acc.x += a.x; acc.y += a.y; acc.z += bb.x; acc.w += bb.y;
        }
    }
    for (; k < end; k++) {
        int c = __ldg(&col[k]);
        uint2 r = hw2[(size_t)c * 16 + j];
        float2 a = __half22float2(*reinterpret_cast<__half2*>(&r.x));
        float2 bb = __half22float2(*reinterpret_cast<__half2*>(&r.y));
        acc.x += a.x; acc.y += a.y; acc.z += bb.x; acc.w += bb.y;
    }
    if (!valid) return;
    float dv = dinv[cn];
    int cb = j * 4;
    float o[4];
    float in[4] = {acc.x * dv, acc.y * dv, acc.z * dv, acc.w * dv};
#pragma unroll
    for (int q = 0; q < 4; q++) {
        int c = cb + q;
        float alpha = g[c] * rsqrtf(rv[c] + 1e-5f);
        float beta = (b[c] - rm[c]) * alpha + be[c];
        o[q] = fmaxf(in[q] * alpha + beta, 0.f);
    }
    int gg = batch[cn];
    red_add_v4(&psum4[gg * 16 + j], make_float4(o[0], o[1], o[2], o[3]));
}

// ---------------- final MLP ----------------
__global__ void mlp_kernel(const float* __restrict__ psum, const float* __restrict__ pcnt,
                           const float* __restrict__ Wf1, const float* __restrict__ bf1,
                           const float* __restrict__ Wf2, const float* __restrict__ bf2,
                           float* __restrict__ out) {
    int g = blockIdx.x;
    int t = threadIdx.x;
    __shared__ float p[64];
    __shared__ float hh[32];
    float cnt = fmaxf(pcnt[g], 1.f);
    float inv = 1.f / cnt;
    p[t] = psum[g * HDIM + t] * inv;
    p[t + 32] = psum[g * HDIM + t + 32] * inv;
    __syncwarp();
    float acc = bf1[t];
#pragma unroll
    for (int k = 0; k < 64; k++)
        acc += p[k] * Wf1[k * 32 + t];
    hh[t] = fmaxf(acc, 0.f);
    __syncwarp();
    if (t < 2) {
        float o = bf2[t];
#pragma unroll
        for (int k = 0; k < 32; k++)
            o += hh[k] * Wf2[k * 2 + t];
        out[g * 2 + t] = 1.f / (1.f + expf(-o));
    }
}

// ---------------- launch ----------------
extern "C" void kernel_launch(void* const* d_in, const int* in_sizes, int n_in,
                              void* d_out, int out_size) {
    const float* x     = (const float*)d_in[0];
    const int*   ei    = (const int*)d_in[1];
    const int*   batch = (const int*)d_in[2];
    const float* W1 = (const float*)d_in[3];
    const float* b1 = (const float*)d_in[4];
    const float* g1 = (const float*)d_in[5];
    const float* be1 = (const float*)d_in[6];
    const float* rm1 = (const float*)d_in[7];
    const float* rv1 = (const float*)d_in[8];
    const float* W2 = (const float*)d_in[9];
    const float* b2 = (const float*)d_in[10];
    const float* g2 = (const float*)d_in[11];
    const float* be2 = (const float*)d_in[12];
    const float* rm2 = (const float*)d_in[13];
    const float* rv2 = (const float*)d_in[14];
    const float* W3 = (const float*)d_in[15];
    const float* b3 = (const float*)d_in[16];
    const float* g3 = (const float*)d_in[17];
    const float* be3 = (const float*)d_in[18];
    const float* rm3 = (const float*)d_in[19];
    const float* rv3 = (const float*)d_in[20];
    const float* Wf1 = (const float*)d_in[21];
    const float* bf1 = (const float*)d_in[22];
    const float* Wf2 = (const float*)d_in[23];
    const float* bf2 = (const float*)d_in[24];

    int n = in_sizes[0] / 5;
    int e = in_sizes[1] / 2;
    int g = out_size / 2;

    const int* srcp = ei;
    const int* dstp = ei + e;

    int *cnt, *rowptr, *cursor, *colp, *bsum;
    float *dinv, *xpad, *aggx, *psum, *pcnt;
    __half *hwA, *hwB;
    cudaGetSymbolAddress((void**)&cnt, d_cnt);
    cudaGetSymbolAddress((void**)&rowptr, d_rowptr);
    cudaGetSymbolAddress((void**)&cursor, d_cursor);
    cudaGetSymbolAddress((void**)&colp, d_col);
    cudaGetSymbolAddress((void**)&bsum, d_blocksum);
    cudaGetSymbolAddress((void**)&dinv, d_dinv);
    cudaGetSymbolAddress((void**)&xpad, d_xpad);
    cudaGetSymbolAddress((void**)&aggx, d_aggx);
    cudaGetSymbolAddress((void**)&hwA, d_hwA);
    cudaGetSymbolAddress((void**)&hwB, d_hwB);
    cudaGetSymbolAddress((void**)&psum, d_psum);
    cudaGetSymbolAddress((void**)&pcnt, d_pcnt);

    const int BS = 256;
    int nb1024 = (n + 1023) / 1024;
    int zero_elems = n > g * HDIM ? n : g * HDIM;

    zero_kernel<<<(zero_elems + BS - 1) / BS, BS>>>(cnt, psum, pcnt, n, g);
    count_kernel<<<(e + BS - 1) / BS, BS>>>(dstp, batch, cnt, pcnt, e, n);
    scan_phase1<<<nb1024, 1024>>>(cnt, rowptr, bsum, dinv, x, xpad, n);
    scan_phase3<<<nb1024, 1024>>>(rowptr, cursor, bsum, n, e);
    scatter_kernel<<<(e + BS - 1) / BS, BS>>>(srcp, dstp, cursor, colp, e);

    // layer 1
    aggx_kernel<<<(n * 2 + BS - 1) / BS, BS>>>(rowptr, colp, dinv, (const float4*)xpad,
                                               (float4*)aggx, n);
    l1_fused<<<(n + 63) / 64, 256>>>(aggx, W1, b1, g1, be1, rm1, rv1, W2, dinv, hwA, n);

    // layer 2
    agg_gemm<<<(n + 63) / 64, 512>>>(rowptr, colp, dinv, (const uint2*)hwA,
                                     b2, g2, be2, rm2, rv2, W3, hwB, n);

    // layer 3
    agg_pool<<<(n * 16 + BS - 1) / BS, BS>>>(rowptr, colp, dinv, (const uint2*)hwB,
                                             b3, g3, be3, rm3, rv3,
                                             batch, (float4*)psum, n);

    mlp_kernel<<<g, 32>>>(psum, pcnt, Wf1, bf1, Wf2, bf2, (float*)d_out);
}

// round 9
// speedup vs baseline: 2.3175x; 1.0314x over previous
#include <cuda_runtime.h>
#include <cuda_fp16.h>
#include <math.h>

#define MAX_N 100000
#define MAX_E 3200000
#define MAX_G 256
#define HDIM 64
#define NB1024 ((MAX_N + 1023) / 1024)

// ---------------- device scratch ----------------
__device__ __align__(16) int    d_cnt[MAX_N];
__device__ __align__(16) int    d_rowptr[MAX_N + 1];
__device__ __align__(16) int    d_cursor[MAX_N];
__device__ __align__(16) int    d_col[MAX_E];
__device__ __align__(16) float  d_dinv[MAX_N];
__device__ __align__(16) int    d_blocksum[NB1024 + 1];
__device__ __align__(16) float  d_xpad[MAX_N * 8];
__device__ __align__(16) float  d_aggx[MAX_N * 8];
__device__ __align__(16) __half d_hwA[MAX_N * HDIM];
__device__ __align__(16) __half d_hwB[MAX_N * HDIM];
__device__ __align__(16) float  d_psum[MAX_G * HDIM];
__device__ __align__(16) float  d_pcnt[MAX_G];

__device__ __forceinline__ void red_add_v4(float4* addr, float4 v) {
    asm volatile("red.global.add.v4.f32 [%0], {%1,%2,%3,%4};"
                 :: "l"(addr), "f"(v.x), "f"(v.y), "f"(v.z), "f"(v.w)
                 : "memory");
}

// ---------------- prep ----------------
__global__ void zero_kernel(int* cnt, float* psum, float* pcnt, int n, int g) {
    int i = blockIdx.x * blockDim.x + threadIdx.x;
    if (i < n) cnt[i] = 0;
    if (i < g * HDIM) psum[i] = 0.f;
    if (i < g) pcnt[i] = 0.f;
}

__global__ void count_kernel(const int* __restrict__ dst, const int* __restrict__ batch,
                             int* __restrict__ cnt, float* __restrict__ pcnt,
                             int nE, int n) {
    int i = blockIdx.x * blockDim.x + threadIdx.x;
    if (i < nE) atomicAdd(&cnt[dst[i]], 1);
    if (i < n) atomicAdd(&pcnt[batch[i]], 1.f);
}

// phase 1: per-block exclusive scan of cnt; also dinv and xpad = x*dinv
__global__ void scan_phase1(const int* __restrict__ cnt, int* __restrict__ rowptr,
                            int* __restrict__ blocksum, float* __restrict__ dinv,
                            const float* __restrict__ x, float* __restrict__ xpad, int n) {
    __shared__ int ws[32];
    int t = threadIdx.x, lane = t & 31, w = t >> 5;
    int i = blockIdx.x * 1024 + t;
    int v = (i < n) ? cnt[i] : 0;
    if (i < n) {
        float dv = rsqrtf((float)v + 1.0f);
        dinv[i] = dv;
        const float* xr = x + (size_t)i * 5;
        float4* xp = reinterpret_cast<float4*>(xpad + (size_t)i * 8);
        xp[0] = make_float4(xr[0] * dv, xr[1] * dv, xr[2] * dv, xr[3] * dv);
        xp[1] = make_float4(xr[4] * dv, 0.f, 0.f, 0.f);
    }
    int incl = v;
#pragma unroll
    for (int o = 1; o < 32; o <<= 1) {
        int xx = __shfl_up_sync(0xffffffffu, incl, o);
        if (lane >= o) incl += xx;
    }
    if (lane == 31) ws[w] = incl;
    __syncthreads();
    if (w == 0) {
        int xx = ws[lane];
        int incl2 = xx;
#pragma unroll
        for (int o = 1; o < 32; o <<= 1) {
            int y = __shfl_up_sync(0xffffffffu, incl2, o);
            if (lane >= o) incl2 += y;
        }
        ws[lane] = incl2 - xx;
    }
    __syncthreads();
    int excl = incl - v + ws[w];
    if (i < n) rowptr[i] = excl;
    if (t == 1023) blocksum[blockIdx.x] = excl + v;
}

// phase 3 (phase 2 merged): each block reduces its prefix of blocksums itself
__global__ void scan_phase3(int* __restrict__ rowptr, int* __restrict__ cursor,
                            const int* __restrict__ bs, int n, int nE) {
    __shared__ int s_off;
    int t = threadIdx.x;
    if (t < 32) {
        int s = 0;
        for (int q = t; q < blockIdx.x; q += 32) s += bs[q];
#pragma unroll
        for (int o = 16; o; o >>= 1) s += __shfl_down_sync(0xffffffffu, s, o);
        if (t == 0) s_off = s;
    }
    __syncthreads();
    int i = blockIdx.x * 1024 + t;
    int off = s_off;
    if (i < n) { int r = rowptr[i] + off; rowptr[i] = r; cursor[i] = r; }
    if (blockIdx.x == 0 && t == 0) rowptr[n] = nE;
}

__global__ void scatter_kernel(const int* __restrict__ src, const int* __restrict__ dst,
                               int* __restrict__ cursor, int* __restrict__ col, int nE) {
    int e = blockIdx.x * blockDim.x + threadIdx.x;
    if (e >= nE) return;
    int idx = atomicAdd(&cursor[dst[e]], 1);
    col[idx] = src[e];
}

// layer-1 aggregation over xpad; 8 thr/node = 4 float2-slots x 2 neighbor halves
__global__ void aggx_kernel(const int* __restrict__ rowptr, const int* __restrict__ col,
                            const float* __restrict__ dinv,
                            const float2* __restrict__ xp2, float2* __restrict__ out2, int n) {
    int t = blockIdx.x * blockDim.x + threadIdx.x;
    int node = t >> 3;
    int lane = threadIdx.x & 31;
    int half = (lane >> 2) & 1;      // neighbor half
    int slot = lane & 3;             // float2 slot (channels 2s..2s+1)
    bool valid = (node < n);
    int cn = valid ? node : (n - 1);

    int beg = rowptr[cn], end = rowptr[cn + 1];
    int mid = (beg + end) >> 1;
    int kb = half ? mid : beg;
    int ke = half ? end : mid;

    float2 acc = make_float2(0.f, 0.f);
    if (half == 0) acc = xp2[(size_t)cn * 4 + slot];   // self term once

    unsigned gmask = 0xFu << (lane & 28);              // this 4-lane half-group
    int k = kb;
#pragma unroll 1
    for (; k + 4 <= ke; k += 4) {
        int cw = __ldg(&col[k + slot]);
        float2 u[4];
#pragma unroll
        for (int q = 0; q < 4; q++) {
            int c = __shfl_sync(gmask, cw, (lane & 28) + q);
            u[q] = xp2[(size_t)c * 4 + slot];
        }
#pragma unroll
        for (int q = 0; q < 4; q++) { acc.x += u[q].x; acc.y += u[q].y; }
    }
    for (; k < ke; k++) {
        int c = __ldg(&col[k]);
        float2 v = xp2[(size_t)c * 4 + slot];
        acc.x += v.x; acc.y += v.y;
    }
    // combine halves (full-warp sync shuffle; all lanes alive)
    acc.x += __shfl_xor_sync(0xffffffffu, acc.x, 4);
    acc.y += __shfl_xor_sync(0xffffffffu, acc.y, 4);
    if (valid && half == 0) {
        float dv = dinv[cn];
        out2[(size_t)cn * 4 + slot] = make_float2(acc.x * dv, acc.y * dv);
    }
}

// layer-1 dense chain: h1 = relu(bn1(aggx@W1+b1)); hwA = (h1@W2)*dinv  (fp16)
__global__ __launch_bounds__(256) void l1_fused(
    const float* __restrict__ aggx, const float* __restrict__ W1,
    const float* __restrict__ b1, const float* __restrict__ g1,
    const float* __restrict__ be1, const float* __restrict__ rm1,
    const float* __restrict__ rv1,
    const float* __restrict__ W2, const float* __restrict__ dinv,
    __half* __restrict__ hw, int n) {
    __shared__ float sW1[5][64];
    __shared__ float alphaS[64], betaS[64];
    __shared__ float sA[64][65];
    __shared__ __align__(16) float sW2[64][64];
    int tid = threadIdx.x;
    int bb = blockIdx.x * 64;

    for (int i = tid; i < 320; i += 256) sW1[i >> 6][i & 63] = W1[i];
    for (int i = tid; i < 4096; i += 256) sW2[i >> 6][i & 63] = W2[i];
    if (tid < 64) {
        float alpha = g1[tid] * rsqrtf(rv1[tid] + 1e-5f);
        alphaS[tid] = alpha;
        betaS[tid] = (b1[tid] - rm1[tid]) * alpha + be1[tid];
    }
    __syncthreads();

    {
        int r = tid >> 2, q = tid & 3;
        int node = bb + r;
        float a0 = 0, a1 = 0, a2 = 0, a3 = 0, a4 = 0;
        if (node < n) {
            const float* ar = aggx + (size_t)node * 8;
            a0 = ar[0]; a1 = ar[1]; a2 = ar[2]; a3 = ar[3]; a4 = ar[4];
        }
#pragma unroll
        for (int q2 = 0; q2 < 16; q2++) {
            int c = q * 16 + q2;
            float acc = a0 * sW1[0][c] + a1 * sW1[1][c] + a2 * sW1[2][c]
                      + a3 * sW1[3][c] + a4 * sW1[4][c];
            sA[r][c] = (node < n) ? fmaxf(acc * alphaS[c] + betaS[c], 0.f) : 0.f;
        }
    }
    __syncthreads();

    int tr = (tid >> 4) * 4;
    int tc = (tid & 15) * 4;
    float acc[4][4];
#pragma unroll
    for (int i = 0; i < 4; i++)
#pragma unroll
        for (int j = 0; j < 4; j++) acc[i][j] = 0.f;
#pragma unroll 8
    for (int k = 0; k < 64; k++) {
        float a0 = sA[tr + 0][k], a1 = sA[tr + 1][k], a2 = sA[tr + 2][k], a3 = sA[tr + 3][k];
        float4 b = *reinterpret_cast<const float4*>(&sW2[k][tc]);
        acc[0][0] += a0 * b.x; acc[0][1] += a0 * b.y; acc[0][2] += a0 * b.z; acc[0][3] += a0 * b.w;
        acc[1][0] += a1 * b.x; acc[1][1] += a1 * b.y; acc[1][2] += a1 * b.z; acc[1][3] += a1 * b.w;
        acc[2][0] += a2 * b.x; acc[2][1] += a2 * b.y; acc[2][2] += a2 * b.z; acc[2][3] += a2 * b.w;
        acc[3][0] += a3 * b.x; acc[3][1] += a3 * b.y; acc[3][2] += a3 * b.z; acc[3][3] += a3 * b.w;
    }
#pragma unroll
    for (int i = 0; i < 4; i++) {
        int node = bb + tr + i;
        if (node >= n) break;
        float dv = dinv[node];
        __half2* hp = reinterpret_cast<__half2*>(hw + (size_t)node * HDIM + tc);
        hp[0] = __floats2half2_rn(acc[i][0] * dv, acc[i][1] * dv);
        hp[1] = __floats2half2_rn(acc[i][2] * dv, acc[i][3] * dv);
    }
}

// fused layer-2: aggregate hwA (warp/node, split halves) + BN + ReLU + @W3 + *dinv -> hwB
// 1024 threads = 32 warps = 32 nodes per block
__global__ __launch_bounds__(1024) void agg_gemm(
    const int* __restrict__ rowptr, const int* __restrict__ col,
    const float* __restrict__ dinv, const uint2* __restrict__ hw2,
    const float* __restrict__ b, const float* __restrict__ g,
    const float* __restrict__ be, const float* __restrict__ rm,
    const float* __restrict__ rv,
    const float* __restrict__ W, __half* __restrict__ hw_out, int n) {
    __shared__ float alphaS[64], betaS[64];
    __shared__ float sA[32][65];
    __shared__ __align__(16) float sW[64][64];
    int tid = threadIdx.x;
    int lane = tid & 31;
    int w = tid >> 5;               // warp = node slot (0..31)
    int bb = blockIdx.x * 32;

    for (int i = tid; i < 4096; i += 1024) sW[i >> 6][i & 63] = W[i];
    if (tid < 64) {
        float alpha = g[tid] * rsqrtf(rv[tid] + 1e-5f);
        alphaS[tid] = alpha;
        betaS[tid] = (b[tid] - rm[tid]) * alpha + be[tid];
    }
    __syncthreads();

    {
        int node = bb + w;
        int cn = (node < n) ? node : (n - 1);
        int half = lane >> 4;          // neighbor half
        int j = lane & 15;             // channel slot (uint2 = 4 channels)
        int beg = rowptr[cn], end = rowptr[cn + 1];
        int mid = (beg + end) >> 1;
        int kb = half ? mid : beg;
        int ke = half ? end : mid;

        float4 acc = make_float4(0.f, 0.f, 0.f, 0.f);
        if (half == 0) {
            uint2 raw = hw2[(size_t)cn * 16 + j];
            float2 f0 = __half22float2(*reinterpret_cast<__half2*>(&raw.x));
            float2 f1 = __half22float2(*reinterpret_cast<__half2*>(&raw.y));
            acc = make_float4(f0.x, f0.y, f1.x, f1.y);
        }
        unsigned gmask = 0xFFFFu << (half << 4);
        int k = kb;
#pragma unroll 1
        for (; k + 8 <= ke; k += 8) {
            int cw = __ldg(&col[k + (j & 7)]);
            uint2 u[8];
#pragma unroll
            for (int q = 0; q < 8; q++) {
                int c = __shfl_sync(gmask, cw, (half << 4) + q);
                u[q] = hw2[(size_t)c * 16 + j];
            }
#pragma unroll
            for (int q = 0; q < 8; q++) {
                float2 a = __half22float2(*reinterpret_cast<__half2*>(&u[q].x));
                float2 bb2 = __half22float2(*reinterpret_cast<__half2*>(&u[q].y));
                acc.x += a.x; acc.y += a.y; acc.z += bb2.x; acc.w += bb2.y;
            }
        }
        for (; k < ke; k++) {
            int c = __ldg(&col[k]);
            uint2 r = hw2[(size_t)c * 16 + j];
            float2 a = __half22float2(*reinterpret_cast<__half2*>(&r.x));
            float2 bb2 = __half22float2(*reinterpret_cast<__half2*>(&r.y));
            acc.x += a.x; acc.y += a.y; acc.z += bb2.x; acc.w += bb2.y;
        }
        // combine halves
        acc.x += __shfl_xor_sync(0xffffffffu, acc.x, 16);
        acc.y += __shfl_xor_sync(0xffffffffu, acc.y, 16);
        acc.z += __shfl_xor_sync(0xffffffffu, acc.z, 16);
        acc.w += __shfl_xor_sync(0xffffffffu, acc.w, 16);
        if (half == 0) {
            float dv = dinv[cn];
            int cb = j * 4;
            float in[4] = {acc.x, acc.y, acc.z, acc.w};
#pragma unroll
            for (int q = 0; q < 4; q++) {
                int c = cb + q;
                sA[w][c] = fmaxf(in[q] * dv * alphaS[c] + betaS[c], 0.f);
            }
        }
    }
    __syncthreads();

    // GEMM 32x64 @ 64x64: 2 outputs/thread
    {
        int r2 = tid >> 5;             // row = warp id
        int c2 = (tid & 31) * 2;       // 2 consecutive cols
        float o0 = 0.f, o1 = 0.f;
#pragma unroll 8
        for (int k = 0; k < 64; k++) {
            float a = sA[r2][k];
            float2 wv = *reinterpret_cast<const float2*>(&sW[k][c2]);
            o0 += a * wv.x; o1 += a * wv.y;
        }
        int node2 = bb + r2;
        if (node2 < n) {
            float dv2 = dinv[node2];
            reinterpret_cast<__half2*>(hw_out + (size_t)node2 * HDIM)[c2 >> 1]
                = __floats2half2_rn(o0 * dv2, o1 * dv2);
        }
    }
}

// layer-3: aggregate (warp/node, split halves) + BN + ReLU + pool
__global__ void agg_pool(const int* __restrict__ rowptr, const int* __restrict__ col,
                         const float* __restrict__ dinv, const uint2* __restrict__ hw2,
                         const float* __restrict__ b, const float* __restrict__ g,
                         const float* __restrict__ be, const float* __restrict__ rm,
                         const float* __restrict__ rv,
                         const int* __restrict__ batch, float4* __restrict__ psum4, int n) {
    int t = blockIdx.x * blockDim.x + threadIdx.x;
    int node = t >> 5;                 // warp per node
    int lane = threadIdx.x & 31;
    int half = lane >> 4;
    int j = lane & 15;
    bool valid = (node < n);
    int cn = valid ? node : (n - 1);

    int beg = rowptr[cn], end = rowptr[cn + 1];
    int mid = (beg + end) >> 1;
    int kb = half ? mid : beg;
    int ke = half ? end : mid;

    float4 acc = make_float4(0.f, 0.f, 0.f, 0.f);
    if (half == 0) {
        uint2 raw = hw2[(size_t)cn * 16 + j];
        float2 f0 = __half22float2(*reinterpret_cast<__half2*>(&raw.x));
        float2 f1 = __half22float2(*reinterpret_cast<__half2*>(&raw.y));
        acc = make_float4(f0.x, f0.y, f1.x, f1.y);
    }
    unsigned gmask = 0xFFFFu << (half << 4);
    int k = kb;
#pragma unroll 1
    for (; k + 8 <= ke; k += 8) {
        int cw = __ldg(&col[k + (j & 7)]);
        uint2 u[8];
#pragma unroll
        for (int q = 0; q < 8; q++) {
            int c = __shfl_sync(gmask, cw, (half << 4) + q);
            u[q] = hw2[(size_t)c * 16 + j];
        }
#pragma unroll
        for (int q = 0; q < 8; q++) {
            float2 a = __half22float2(*reinterpret_cast<__half2*>(&u[q].x));
            float2 bb2 = __half22float2(*reinterpret_cast<__half2*>(&u[q].y));
            acc.x += a.x; acc.y += a.y; acc.z += bb2.x; acc.w += bb2.y;
        }
    }
    for (; k < ke; k++) {
        int c = __ldg(&col[k]);
        uint2 r = hw2[(size_t)c * 16 + j];
        float2 a = __half22float2(*reinterpret_cast<__half2*>(&r.x));
        float2 bb2 = __half22float2(*reinterpret_cast<__half2*>(&r.y));
        acc.x += a.x; acc.y += a.y; acc.z += bb2.x; acc.w += bb2.y;
    }
    acc.x += __shfl_xor_sync(0xffffffffu, acc.x, 16);
    acc.y += __shfl_xor_sync(0xffffffffu, acc.y, 16);
    acc.z += __shfl_xor_sync(0xffffffffu, acc.z, 16);
    acc.w += __shfl_xor_sync(0xffffffffu, acc.w, 16);
    if (!valid || half != 0) return;
    float dv = dinv[cn];
    int cb = j * 4;
    float o[4];
    float in[4] = {acc.x * dv, acc.y * dv, acc.z * dv, acc.w * dv};
#pragma unroll
    for (int q = 0; q < 4; q++) {
        int c = cb + q;
        float alpha = g[c] * rsqrtf(rv[c] + 1e-5f);
        float beta = (b[c] - rm[c]) * alpha + be[c];
        o[q] = fmaxf(in[q] * alpha + beta, 0.f);
    }
    int gg = batch[cn];
    red_add_v4(&psum4[gg * 16 + j], make_float4(o[0], o[1], o[2], o[3]));
}

// ---------------- final MLP ----------------
__global__ void mlp_kernel(const float* __restrict__ psum, const float* __restrict__ pcnt,
                           const float* __restrict__ Wf1, const float* __restrict__ bf1,
                           const float* __restrict__ Wf2, const float* __restrict__ bf2,
                           float* __restrict__ out) {
    int g = blockIdx.x;
    int t = threadIdx.x;
    __shared__ float p[64];
    __shared__ float hh[32];
    float cnt = fmaxf(pcnt[g], 1.f);
    float inv = 1.f / cnt;
    p[t] = psum[g * HDIM + t] * inv;
    p[t + 32] = psum[g * HDIM + t + 32] * inv;
    __syncwarp();
    float acc = bf1[t];
#pragma unroll
    for (int k = 0; k < 64; k++)
        acc += p[k] * Wf1[k * 32 + t];
    hh[t] = fmaxf(acc, 0.f);
    __syncwarp();
    if (t < 2) {
        float o = bf2[t];
#pragma unroll
        for (int k = 0; k < 32; k++)
            o += hh[k] * Wf2[k * 2 + t];
        out[g * 2 + t] = 1.f / (1.f + expf(-o));
    }
}

// ---------------- launch ----------------
extern "C" void kernel_launch(void* const* d_in, const int* in_sizes, int n_in,
                              void* d_out, int out_size) {
    const float* x     = (const float*)d_in[0];
    const int*   ei    = (const int*)d_in[1];
    const int*   batch = (const int*)d_in[2];
    const float* W1 = (const float*)d_in[3];
    const float* b1 = (const float*)d_in[4];
    const float* g1 = (const float*)d_in[5];
    const float* be1 = (const float*)d_in[6];
    const float* rm1 = (const float*)d_in[7];
    const float* rv1 = (const float*)d_in[8];
    const float* W2 = (const float*)d_in[9];
    const float* b2 = (const float*)d_in[10];
    const float* g2 = (const float*)d_in[11];
    const float* be2 = (const float*)d_in[12];
    const float* rm2 = (const float*)d_in[13];
    const float* rv2 = (const float*)d_in[14];
    const float* W3 = (const float*)d_in[15];
    const float* b3 = (const float*)d_in[16];
    const float* g3 = (const float*)d_in[17];
    const float* be3 = (const float*)d_in[18];
    const float* rm3 = (const float*)d_in[19];
    const float* rv3 = (const float*)d_in[20];
    const float* Wf1 = (const float*)d_in[21];
    const float* bf1 = (const float*)d_in[22];
    const float* Wf2 = (const float*)d_in[23];
    const float* bf2 = (const float*)d_in[24];

    int n = in_sizes[0] / 5;
    int e = in_sizes[1] / 2;
    int g = out_size / 2;

    const int* srcp = ei;
    const int* dstp = ei + e;

    int *cnt, *rowptr, *cursor, *colp, *bsum;
    float *dinv, *xpad, *aggx, *psum, *pcnt;
    __half *hwA, *hwB;
    cudaGetSymbolAddress((void**)&cnt, d_cnt);
    cudaGetSymbolAddress((void**)&rowptr, d_rowptr);
    cudaGetSymbolAddress((void**)&cursor, d_cursor);
    cudaGetSymbolAddress((void**)&colp, d_col);
    cudaGetSymbolAddress((void**)&bsum, d_blocksum);
    cudaGetSymbolAddress((void**)&dinv, d_dinv);
    cudaGetSymbolAddress((void**)&xpad, d_xpad);
    cudaGetSymbolAddress((void**)&aggx, d_aggx);
    cudaGetSymbolAddress((void**)&hwA, d_hwA);
    cudaGetSymbolAddress((void**)&hwB, d_hwB);
    cudaGetSymbolAddress((void**)&psum, d_psum);
    cudaGetSymbolAddress((void**)&pcnt, d_pcnt);

    const int BS = 256;
    int nb1024 = (n + 1023) / 1024;
    int zero_elems = n > g * HDIM ? n : g * HDIM;

    zero_kernel<<<(zero_elems + BS - 1) / BS, BS>>>(cnt, psum, pcnt, n, g);
    count_kernel<<<(e + BS - 1) / BS, BS>>>(dstp, batch, cnt, pcnt, e, n);
    scan_phase1<<<nb1024, 1024>>>(cnt, rowptr, bsum, dinv, x, xpad, n);
    scan_phase3<<<nb1024, 1024>>>(rowptr, cursor, bsum, n, e);
    scatter_kernel<<<(e + BS - 1) / BS, BS>>>(srcp, dstp, cursor, colp, e);

    // layer 1
    aggx_kernel<<<((long long)n * 8 + BS - 1) / BS, BS>>>(rowptr, colp, dinv,
                                                          (const float2*)xpad,
                                                          (float2*)aggx, n);
    l1_fused<<<(n + 63) / 64, 256>>>(aggx, W1, b1, g1, be1, rm1, rv1, W2, dinv, hwA, n);

    // layer 2
    agg_gemm<<<(n + 31) / 32, 1024>>>(rowptr, colp, dinv, (const uint2*)hwA,
                                      b2, g2, be2, rm2, rv2, W3, hwB, n);

    // layer 3
    agg_pool<<<((long long)n * 32 + BS - 1) / BS, BS>>>(rowptr, colp, dinv, (const uint2*)hwB,
                                                        b3, g3, be3, rm3, rv3,
                                                        batch, (float4*)psum, n);

    mlp_kernel<<<g, 32>>>(psum, pcnt, Wf1, bf1, Wf2, bf2, (float*)d_out);
}